// round 6
// baseline (speedup 1.0000x reference)
#include <cuda_runtime.h>
#include <cuda_bf16.h>
#include <cstdint>

#define D 128
#define MAXN 50000
#define MAXE 600000
#define EPSV 1e-5f

typedef unsigned long long ull;

// ---------------- scratch ----------------
__device__ int   g_cnt[MAXN];
__device__ int   g_start[MAXN];
__device__ float g_dis[MAXN];
__device__ int   g_srow[MAXE];
__device__ float g_bufH[(size_t)MAXN * D];   // GEMM output (float)
__device__ float g_bufB[(size_t)MAXN * D];   // layer2 relu output (float)
__device__ __nv_bfloat16 g_Ahi[(size_t)MAXN * D];
__device__ __nv_bfloat16 g_Alo[(size_t)MAXN * D];
__device__ __nv_bfloat16 g_WThi1[D * D];
__device__ __nv_bfloat16 g_WTlo1[D * D];
__device__ __nv_bfloat16 g_WThi2[D * D];
__device__ __nv_bfloat16 g_WTlo2[D * D];
__device__ float g_sum[D];
__device__ float g_sumsq[D];

// ---------------- helpers ----------------
__device__ __forceinline__ uint32_t smem_u32(const void* p) {
    uint32_t a;
    asm("{ .reg .u64 t; cvta.to.shared.u64 t, %1; cvt.u32.u64 %0, t; }"
        : "=r"(a) : "l"(p));
    return a;
}

#define LDSM4(r0, r1, r2, r3, addr) \
    asm volatile("ldmatrix.sync.aligned.m8n8.x4.shared.b16 {%0,%1,%2,%3}, [%4];" \
        : "=r"(r0), "=r"(r1), "=r"(r2), "=r"(r3) : "r"(addr))

#define MMA_BF16(d, a, b) \
    asm volatile("mma.sync.aligned.m16n8k16.row.col.f32.bf16.bf16.f32 " \
        "{%0,%1,%2,%3}, {%4,%5,%6,%7}, {%8,%9}, {%0,%1,%2,%3};" \
        : "+f"((d)[0]), "+f"((d)[1]), "+f"((d)[2]), "+f"((d)[3]) \
        : "r"((a)[0]), "r"((a)[1]), "r"((a)[2]), "r"((a)[3]), \
          "r"((b)[0]), "r"((b)[1]))

__device__ __forceinline__ void split_bf16(float v, __nv_bfloat16& h, __nv_bfloat16& l) {
    h = __float2bfloat16_rn(v);
    l = __float2bfloat16_rn(v - __bfloat162float(h));
}

// ---------------- merged prep: zero cnt + split W1/W2/x ------------------
__global__ void k_prep(const float* __restrict__ W1,
                       const float* __restrict__ W2,
                       const float* __restrict__ x,
                       int n, int total4) {
    int i = blockIdx.x * blockDim.x + threadIdx.x;
    if (i < n) g_cnt[i] = 0;
    if (i < D * D) {
        int k = i >> 7, nn = i & 127;
        __nv_bfloat16 h, l;
        split_bf16(W1[i], h, l);
        g_WThi1[nn * D + k] = h;
        g_WTlo1[nn * D + k] = l;
        split_bf16(W2[i], h, l);
        g_WThi2[nn * D + k] = h;
        g_WTlo2[nn * D + k] = l;
    }
    if (i < total4) {
        float4 v = ((const float4*)x)[i];
        __nv_bfloat16 h[4], l[4];
        split_bf16(v.x, h[0], l[0]);
        split_bf16(v.y, h[1], l[1]);
        split_bf16(v.z, h[2], l[2]);
        split_bf16(v.w, h[3], l[3]);
        *(uint2*)(g_Ahi + (size_t)i * 4) = *(uint2*)h;
        *(uint2*)(g_Alo + (size_t)i * 4) = *(uint2*)l;
    }
}

__global__ void k_deg(const int* __restrict__ cols, int e) {
    int i = blockIdx.x * blockDim.x + threadIdx.x;
    if (i < e) atomicAdd(&g_cnt[cols[i]], 1);
}

// single-block scan: g_cnt -> g_start (exclusive), g_dis, reset g_cnt, zero stats
__global__ void __launch_bounds__(1024) k_scanall(int n) {
    __shared__ int sh[1024];
    int t = threadIdx.x;
    int chunk = (n + 1023) >> 10;
    int lo = t * chunk;
    int hi = min(lo + chunk, n);
    int s = 0;
    for (int i = lo; i < hi; ++i) s += g_cnt[i];
    sh[t] = s;
    __syncthreads();
    #pragma unroll
    for (int off = 1; off < 1024; off <<= 1) {
        int v = (t >= off) ? sh[t - off] : 0;
        __syncthreads();
        sh[t] += v;
        __syncthreads();
    }
    int run = (t == 0) ? 0 : sh[t - 1];
    for (int i = lo; i < hi; ++i) {
        int c = g_cnt[i];
        g_start[i] = run;
        run += c;
        g_dis[i] = rsqrtf((float)c + 1.0f);
        g_cnt[i] = 0;
    }
    if (t < D) { g_sum[t] = 0.f; g_sumsq[t] = 0.f; }
}

__global__ void k_scatter(const int* __restrict__ rows,
                          const int* __restrict__ cols, int e) {
    int i = blockIdx.x * blockDim.x + threadIdx.x;
    if (i < e) {
        int c = cols[i];
        int p = g_start[c] + atomicAdd(&g_cnt[c], 1);
        g_srow[p] = rows[i];
    }
}

// ---------------- bf16 mma.sync GEMM, fully-staged, sync-free mainloop ---
#define TSTRIDE 136   // bf16 units; 272B rows -> 4-bank steps, conflict-free LDSM
#define SM_AHI 0
#define SM_ALO 34816
#define SM_WHI 69632
#define SM_WLO 104448
#define GEMM_SMEM 139264

__global__ void __launch_bounds__(256, 1)
k_gemm_mma(const __nv_bfloat16* __restrict__ Ahi,
           const __nv_bfloat16* __restrict__ Alo,
           const __nv_bfloat16* __restrict__ Whi,
           const __nv_bfloat16* __restrict__ Wlo,
           float* __restrict__ C, int n) {
    extern __shared__ __align__(16) char sm[];
    uint32_t sb = smem_u32(sm);
    int t = threadIdx.x, lane = t & 31, wid = t >> 5;
    int r0 = blockIdx.x * 128;
    int wm = (wid >> 1) * 32;
    int wn = (wid & 1) * 64;

    // ---- stage EVERYTHING once: A hi/lo [128][128], W hi/lo [128][128] ----
    {
        int row = t >> 1, half = t & 1;
        int arg = r0 + row; if (arg >= n) arg = n - 1;
        const uint4* gah = (const uint4*)(Ahi + (size_t)arg * D + half * 64);
        const uint4* gal = (const uint4*)(Alo + (size_t)arg * D + half * 64);
        const uint4* gwh = (const uint4*)(Whi + row * D + half * 64);
        const uint4* gwl = (const uint4*)(Wlo + row * D + half * 64);
        uint4* sah = (uint4*)(sm + SM_AHI + (row * TSTRIDE + half * 64) * 2);
        uint4* sal = (uint4*)(sm + SM_ALO + (row * TSTRIDE + half * 64) * 2);
        uint4* swh = (uint4*)(sm + SM_WHI + (row * TSTRIDE + half * 64) * 2);
        uint4* swl = (uint4*)(sm + SM_WLO + (row * TSTRIDE + half * 64) * 2);
        #pragma unroll
        for (int j = 0; j < 8; ++j) {
            sah[j] = gah[j]; sal[j] = gal[j];
            swh[j] = gwh[j]; swl[j] = gwl[j];
        }
    }
    __syncthreads();          // the only barrier

    // ldmatrix lane address components
    int qa = lane >> 3, la = lane & 7;
    int ra = (qa & 1) * 8 + la;          // A row within m16 tile
    int ka = (qa >> 1) * 8;              // A k-half offset
    int nb = (qa >> 1) * 8 + la;         // B n within pair
    int kb = (qa & 1) * 8;               // B k-half offset

    uint32_t aHiB = sb + SM_AHI + ((wm + ra) * TSTRIDE + ka) * 2;
    uint32_t aLoB = sb + SM_ALO + ((wm + ra) * TSTRIDE + ka) * 2;
    uint32_t bHiB = sb + SM_WHI + ((wn + nb) * TSTRIDE + kb) * 2;
    uint32_t bLoB = sb + SM_WLO + ((wn + nb) * TSTRIDE + kb) * 2;

    float acc[2][8][4];
    #pragma unroll
    for (int mt = 0; mt < 2; ++mt)
        #pragma unroll
        for (int nt = 0; nt < 8; ++nt)
            #pragma unroll
            for (int q = 0; q < 4; ++q) acc[mt][nt][q] = 0.f;

    #pragma unroll
    for (int kc = 0; kc < 8; ++kc) {          // 8 x k16 steps, no syncs
        uint32_t ah[2][4], al[2][4], bh[8][2], bl[8][2];
        #pragma unroll
        for (int mt = 0; mt < 2; ++mt) {
            uint32_t ao = (uint32_t)(mt * 16 * TSTRIDE * 2 + kc * 32);
            LDSM4(ah[mt][0], ah[mt][1], ah[mt][2], ah[mt][3], aHiB + ao);
            LDSM4(al[mt][0], al[mt][1], al[mt][2], al[mt][3], aLoB + ao);
        }
        #pragma unroll
        for (int p = 0; p < 4; ++p) {
            uint32_t bo = (uint32_t)(p * 16 * TSTRIDE * 2 + kc * 32);
            LDSM4(bh[2*p][0], bh[2*p][1], bh[2*p+1][0], bh[2*p+1][1], bHiB + bo);
            LDSM4(bl[2*p][0], bl[2*p][1], bl[2*p+1][0], bl[2*p+1][1], bLoB + bo);
        }
        #pragma unroll
        for (int mt = 0; mt < 2; ++mt)
            #pragma unroll
            for (int nt = 0; nt < 8; ++nt) {
                MMA_BF16(acc[mt][nt], ah[mt], bh[nt]);
                MMA_BF16(acc[mt][nt], al[mt], bh[nt]);
                MMA_BF16(acc[mt][nt], ah[mt], bl[nt]);
            }
    }

    int tr = lane >> 2, tc = (lane & 3) * 2;
    #pragma unroll
    for (int mt = 0; mt < 2; ++mt)
        #pragma unroll
        for (int nt = 0; nt < 8; ++nt) {
            int row = r0 + wm + mt * 16 + tr;
            int col = wn + nt * 8 + tc;
            if (row < n)
                *(float2*)(C + (size_t)row * D + col) =
                    make_float2(acc[mt][nt][0], acc[mt][nt][1]);
            if (row + 8 < n)
                *(float2*)(C + (size_t)(row + 8) * D + col) =
                    make_float2(acc[mt][nt][2], acc[mt][nt][3]);
        }
}

// -------- aggregation: warp per node, 4-way unrolled, fused epilogue -----
__global__ void __launch_bounds__(256) k_agg(const float* __restrict__ h,
                                             const float* __restrict__ b,
                                             float* __restrict__ outF,
                                             __nv_bfloat16* __restrict__ outHi,
                                             __nv_bfloat16* __restrict__ outLo,
                                             int n, int do_stats) {
    __shared__ float s_sum[D];
    __shared__ float s_sq[D];
    int tid  = threadIdx.x;
    int lane = tid & 31;
    int wid  = tid >> 5;
    if (do_stats) {
        if (tid < D) { s_sum[tid] = 0.f; s_sq[tid] = 0.f; }
        __syncthreads();
    }
    float4 b4 = *(const float4*)(b + lane * 4);

    for (int c = blockIdx.x * 8 + wid; c < n; c += gridDim.x * 8) {
        int s0  = g_start[c];
        int end = s0 + g_cnt[c];
        float4 a0 = make_float4(0.f, 0.f, 0.f, 0.f);
        float4 a1 = a0, a2 = a0, a3 = a0;
        int j = s0;
        for (; j + 4 <= end; j += 4) {
            int r0 = __ldg(&g_srow[j]);
            int r1 = __ldg(&g_srow[j + 1]);
            int r2 = __ldg(&g_srow[j + 2]);
            int r3 = __ldg(&g_srow[j + 3]);
            float d0 = __ldg(&g_dis[r0]);
            float d1 = __ldg(&g_dis[r1]);
            float d2 = __ldg(&g_dis[r2]);
            float d3 = __ldg(&g_dis[r3]);
            float4 v0 = *(const float4*)(h + (size_t)r0 * D + lane * 4);
            float4 v1 = *(const float4*)(h + (size_t)r1 * D + lane * 4);
            float4 v2 = *(const float4*)(h + (size_t)r2 * D + lane * 4);
            float4 v3 = *(const float4*)(h + (size_t)r3 * D + lane * 4);
            a0.x = fmaf(v0.x, d0, a0.x); a0.y = fmaf(v0.y, d0, a0.y);
            a0.z = fmaf(v0.z, d0, a0.z); a0.w = fmaf(v0.w, d0, a0.w);
            a1.x = fmaf(v1.x, d1, a1.x); a1.y = fmaf(v1.y, d1, a1.y);
            a1.z = fmaf(v1.z, d1, a1.z); a1.w = fmaf(v1.w, d1, a1.w);
            a2.x = fmaf(v2.x, d2, a2.x); a2.y = fmaf(v2.y, d2, a2.y);
            a2.z = fmaf(v2.z, d2, a2.z); a2.w = fmaf(v2.w, d2, a2.w);
            a3.x = fmaf(v3.x, d3, a3.x); a3.y = fmaf(v3.y, d3, a3.y);
            a3.z = fmaf(v3.z, d3, a3.z); a3.w = fmaf(v3.w, d3, a3.w);
        }
        for (; j < end; ++j) {
            int   rr = __ldg(&g_srow[j]);
            float dr = __ldg(&g_dis[rr]);
            float4 v = *(const float4*)(h + (size_t)rr * D + lane * 4);
            a0.x = fmaf(v.x, dr, a0.x); a0.y = fmaf(v.y, dr, a0.y);
            a0.z = fmaf(v.z, dr, a0.z); a0.w = fmaf(v.w, dr, a0.w);
        }
        float4 acc;
        acc.x = (a0.x + a1.x) + (a2.x + a3.x);
        acc.y = (a0.y + a1.y) + (a2.y + a3.y);
        acc.z = (a0.z + a1.z) + (a2.z + a3.z);
        acc.w = (a0.w + a1.w) + (a2.w + a3.w);

        float dc = g_dis[c];
        float sc = dc * dc;
        float4 hc = *(const float4*)(h + (size_t)c * D + lane * 4);
        float4 r4;
        r4.x = fmaxf(fmaf(acc.x, dc, fmaf(hc.x, sc, b4.x)), 0.f);
        r4.y = fmaxf(fmaf(acc.y, dc, fmaf(hc.y, sc, b4.y)), 0.f);
        r4.z = fmaxf(fmaf(acc.z, dc, fmaf(hc.z, sc, b4.z)), 0.f);
        r4.w = fmaxf(fmaf(acc.w, dc, fmaf(hc.w, sc, b4.w)), 0.f);
        if (do_stats) {
            *(float4*)(outF + (size_t)c * D + lane * 4) = r4;
            int d0 = lane * 4;
            atomicAdd(&s_sum[d0 + 0], r4.x); atomicAdd(&s_sq[d0 + 0], r4.x * r4.x);
            atomicAdd(&s_sum[d0 + 1], r4.y); atomicAdd(&s_sq[d0 + 1], r4.y * r4.y);
            atomicAdd(&s_sum[d0 + 2], r4.z); atomicAdd(&s_sq[d0 + 2], r4.z * r4.z);
            atomicAdd(&s_sum[d0 + 3], r4.w); atomicAdd(&s_sq[d0 + 3], r4.w * r4.w);
        } else {
            __nv_bfloat16 hh[4], ll[4];
            split_bf16(r4.x, hh[0], ll[0]);
            split_bf16(r4.y, hh[1], ll[1]);
            split_bf16(r4.z, hh[2], ll[2]);
            split_bf16(r4.w, hh[3], ll[3]);
            *(uint2*)(outHi + (size_t)c * D + lane * 4) = *(uint2*)hh;
            *(uint2*)(outLo + (size_t)c * D + lane * 4) = *(uint2*)ll;
        }
    }
    if (do_stats) {
        __syncthreads();
        if (tid < D) {
            atomicAdd(&g_sum[tid], s_sum[tid]);
            atomicAdd(&g_sumsq[tid], s_sq[tid]);
        }
    }
}

// ---------------- BatchNorm apply ----------------
__global__ void k_bn(const float* __restrict__ h,
                     const float* __restrict__ gamma,
                     const float* __restrict__ beta,
                     float* __restrict__ out, int n) {
    int idx = blockIdx.x * blockDim.x + threadIdx.x;
    int total = n * (D / 4);
    if (idx >= total) return;
    int d0 = (idx & 31) * 4;
    float invN = 1.0f / (float)n;
    float4 v = ((const float4*)h)[idx];
    float vv[4] = {v.x, v.y, v.z, v.w};
    float res[4];
    #pragma unroll
    for (int s = 0; s < 4; ++s) {
        int d = d0 + s;
        float m   = g_sum[d] * invN;
        float var = g_sumsq[d] * invN - m * m;
        float inv = rsqrtf(var + EPSV);
        res[s] = gamma[d] * (vv[s] - m) * inv + beta[d];
    }
    ((float4*)out)[idx] = make_float4(res[0], res[1], res[2], res[3]);
}

// ---------------- launch ----------------
extern "C" void kernel_launch(void* const* d_in, const int* in_sizes, int n_in,
                              void* d_out, int out_size) {
    const float* x     = (const float*)d_in[0];
    const int*   ei    = (const int*)d_in[1];
    const float* W1    = (const float*)d_in[2];
    const float* b1    = (const float*)d_in[3];
    const float* W2    = (const float*)d_in[4];
    const float* b2    = (const float*)d_in[5];
    const float* gamma = (const float*)d_in[6];
    const float* beta  = (const float*)d_in[7];
    float* out = (float*)d_out;

    int n = in_sizes[0] / D;
    int e = in_sizes[1] / 2;
    const int* rows = ei;
    const int* cols = ei + e;
    int total4 = n * (D / 4);

    float *bufH, *bufB;
    __nv_bfloat16 *ahi, *alo, *wh1, *wl1, *wh2, *wl2;
    cudaGetSymbolAddress((void**)&bufH, g_bufH);
    cudaGetSymbolAddress((void**)&bufB, g_bufB);
    cudaGetSymbolAddress((void**)&ahi, g_Ahi);
    cudaGetSymbolAddress((void**)&alo, g_Alo);
    cudaGetSymbolAddress((void**)&wh1, g_WThi1);
    cudaGetSymbolAddress((void**)&wl1, g_WTlo1);
    cudaGetSymbolAddress((void**)&wh2, g_WThi2);
    cudaGetSymbolAddress((void**)&wl2, g_WTlo2);

    cudaFuncSetAttribute(k_gemm_mma, cudaFuncAttributeMaxDynamicSharedMemorySize,
                         GEMM_SMEM);

    int tb = 256;
    int nb_e    = (e + tb - 1) / tb;
    int nb_f4   = (total4 + tb - 1) / tb;
    int gemm_grid = (n + 127) / 128;
    int agg_grid = 2048;

    // 1: merged prep (zero cnt + split W1/W2/x)
    k_prep<<<nb_f4, tb>>>(W1, W2, x, n, total4);
    // 2: degree histogram
    k_deg<<<nb_e, tb>>>(cols, e);
    // 3: scan + dis
    k_scanall<<<1, 1024>>>(n);
    // 4: layer-1 GEMM  (<-- profiler capture slot)
    k_gemm_mma<<<gemm_grid, 256, GEMM_SMEM>>>(ahi, alo, wh1, wl1, bufH, n);
    // 5: CSR scatter
    k_scatter<<<nb_e, tb>>>(rows, cols, e);
    // 6: layer-1 aggregation -> bf16 hi/lo
    k_agg<<<agg_grid, 256>>>(bufH, b1, nullptr, ahi, alo, n, 0);
    // 7: layer-2 GEMM
    k_gemm_mma<<<gemm_grid, 256, GEMM_SMEM>>>(ahi, alo, wh2, wl2, bufH, n);
    // 8: layer-2 aggregation -> float + stats
    k_agg<<<agg_grid, 256>>>(bufH, b2, bufB, nullptr, nullptr, n, 1);
    // 9: batchnorm
    k_bn<<<nb_f4, tb>>>(bufB, gamma, beta, out, n);
}

// round 7
// speedup vs baseline: 1.0841x; 1.0841x over previous
#include <cuda_runtime.h>
#include <cuda_bf16.h>
#include <cstdint>

#define D 128
#define MAXN 50000
#define MAXE 600000
#define EPSV 1e-5f

typedef unsigned long long ull;

// ---------------- scratch (zero-initialized at module load; every graph
// replay restores zeros via k_cleanup -> deterministic) ----------------
__device__ int   g_cnt[MAXN];     // degree histogram (persists through replay)
__device__ int   g_cur[MAXN];     // scatter cursor
__device__ int   g_start[MAXN];
__device__ float g_dis[MAXN];
__device__ int   g_srow[MAXE];
__device__ float g_out[(size_t)MAXN * D];        // gemm output (fp32)
__device__ __nv_bfloat16 g_Yhi[(size_t)MAXN * D];
__device__ __nv_bfloat16 g_Ylo[(size_t)MAXN * D];
__device__ __nv_bfloat16 g_WThi1[D * D];
__device__ __nv_bfloat16 g_WTlo1[D * D];
__device__ __nv_bfloat16 g_WThi2[D * D];
__device__ __nv_bfloat16 g_WTlo2[D * D];
__device__ float g_sum[D];
__device__ float g_sumsq[D];

// ---------------- helpers ----------------
__device__ __forceinline__ uint32_t smem_u32(const void* p) {
    uint32_t a;
    asm("{ .reg .u64 t; cvta.to.shared.u64 t, %1; cvt.u32.u64 %0, t; }"
        : "=r"(a) : "l"(p));
    return a;
}

#define LDSM4(r0, r1, r2, r3, addr) \
    asm volatile("ldmatrix.sync.aligned.m8n8.x4.shared.b16 {%0,%1,%2,%3}, [%4];" \
        : "=r"(r0), "=r"(r1), "=r"(r2), "=r"(r3) : "r"(addr))

#define MMA_BF16(d, a, b) \
    asm volatile("mma.sync.aligned.m16n8k16.row.col.f32.bf16.bf16.f32 " \
        "{%0,%1,%2,%3}, {%4,%5,%6,%7}, {%8,%9}, {%0,%1,%2,%3};" \
        : "+f"((d)[0]), "+f"((d)[1]), "+f"((d)[2]), "+f"((d)[3]) \
        : "r"((a)[0]), "r"((a)[1]), "r"((a)[2]), "r"((a)[3]), \
          "r"((b)[0]), "r"((b)[1]))

__device__ __forceinline__ void split_bf16(float v, __nv_bfloat16& h, __nv_bfloat16& l) {
    h = __float2bfloat16_rn(v);
    l = __float2bfloat16_rn(v - __bfloat162float(h));
}

// ---------------- 1: degree histogram (g_cnt starts at 0) ----------------
__global__ void k_deg(const int* __restrict__ cols, int e) {
    int i = blockIdx.x * blockDim.x + threadIdx.x;
    if (i < e) atomicAdd(&g_cnt[cols[i]], 1);
}

// ---------------- 2: single-block scan (keeps g_cnt intact) --------------
__global__ void __launch_bounds__(1024) k_scanall(int n) {
    __shared__ int sh[1024];
    int t = threadIdx.x;
    int chunk = (n + 1023) >> 10;
    int lo = t * chunk;
    int hi = min(lo + chunk, n);
    int s = 0;
    for (int i = lo; i < hi; ++i) s += g_cnt[i];
    sh[t] = s;
    __syncthreads();
    #pragma unroll
    for (int off = 1; off < 1024; off <<= 1) {
        int v = (t >= off) ? sh[t - off] : 0;
        __syncthreads();
        sh[t] += v;
        __syncthreads();
    }
    int run = (t == 0) ? 0 : sh[t - 1];
    for (int i = lo; i < hi; ++i) {
        int c = g_cnt[i];
        g_start[i] = run;
        run += c;
        g_dis[i] = rsqrtf((float)c + 1.0f);   // +1 self loop
    }
}

// ---------------- 3: CSR scatter (g_cur starts at 0) ---------------------
__global__ void k_scatter(const int* __restrict__ rows,
                          const int* __restrict__ cols, int e) {
    int i = blockIdx.x * blockDim.x + threadIdx.x;
    if (i < e) {
        int c = cols[i];
        int p = g_start[c] + atomicAdd(&g_cur[c], 1);
        g_srow[p] = rows[i];
    }
}

// ---------------- 4/7: aggregation Y = A_hat * src -----------------------
// warp per node; edge indices + dis loaded lane-parallel, shfl-broadcast.
// epilogue: split to bf16 hi/lo for the following GEMM.
__global__ void __launch_bounds__(256) k_agg(const float* __restrict__ src,
                                             __nv_bfloat16* __restrict__ outHi,
                                             __nv_bfloat16* __restrict__ outLo,
                                             int n) {
    int tid  = threadIdx.x;
    int lane = tid & 31;
    int wid  = tid >> 5;

    for (int c = blockIdx.x * 8 + wid; c < n; c += gridDim.x * 8) {
        int s0  = g_start[c];
        int deg = g_cnt[c];
        float4 a0 = make_float4(0.f, 0.f, 0.f, 0.f);
        float4 a1 = a0, a2 = a0, a3 = a0;

        for (int base = 0; base < deg; base += 32) {
            int m = min(32, deg - base);
            int rj = 0; float dj = 0.f;
            if (lane < m) {
                rj = __ldg(&g_srow[s0 + base + lane]);
                dj = __ldg(&g_dis[rj]);
            }
            int k = 0;
            for (; k + 4 <= m; k += 4) {
                int r0 = __shfl_sync(0xFFFFFFFFu, rj, k);
                int r1 = __shfl_sync(0xFFFFFFFFu, rj, k + 1);
                int r2 = __shfl_sync(0xFFFFFFFFu, rj, k + 2);
                int r3 = __shfl_sync(0xFFFFFFFFu, rj, k + 3);
                float d0 = __shfl_sync(0xFFFFFFFFu, dj, k);
                float d1 = __shfl_sync(0xFFFFFFFFu, dj, k + 1);
                float d2 = __shfl_sync(0xFFFFFFFFu, dj, k + 2);
                float d3 = __shfl_sync(0xFFFFFFFFu, dj, k + 3);
                float4 v0 = *(const float4*)(src + (size_t)r0 * D + lane * 4);
                float4 v1 = *(const float4*)(src + (size_t)r1 * D + lane * 4);
                float4 v2 = *(const float4*)(src + (size_t)r2 * D + lane * 4);
                float4 v3 = *(const float4*)(src + (size_t)r3 * D + lane * 4);
                a0.x = fmaf(v0.x, d0, a0.x); a0.y = fmaf(v0.y, d0, a0.y);
                a0.z = fmaf(v0.z, d0, a0.z); a0.w = fmaf(v0.w, d0, a0.w);
                a1.x = fmaf(v1.x, d1, a1.x); a1.y = fmaf(v1.y, d1, a1.y);
                a1.z = fmaf(v1.z, d1, a1.z); a1.w = fmaf(v1.w, d1, a1.w);
                a2.x = fmaf(v2.x, d2, a2.x); a2.y = fmaf(v2.y, d2, a2.y);
                a2.z = fmaf(v2.z, d2, a2.z); a2.w = fmaf(v2.w, d2, a2.w);
                a3.x = fmaf(v3.x, d3, a3.x); a3.y = fmaf(v3.y, d3, a3.y);
                a3.z = fmaf(v3.z, d3, a3.z); a3.w = fmaf(v3.w, d3, a3.w);
            }
            for (; k < m; ++k) {
                int   rr = __shfl_sync(0xFFFFFFFFu, rj, k);
                float dr = __shfl_sync(0xFFFFFFFFu, dj, k);
                float4 v = *(const float4*)(src + (size_t)rr * D + lane * 4);
                a0.x = fmaf(v.x, dr, a0.x); a0.y = fmaf(v.y, dr, a0.y);
                a0.z = fmaf(v.z, dr, a0.z); a0.w = fmaf(v.w, dr, a0.w);
            }
        }
        float4 acc;
        acc.x = (a0.x + a1.x) + (a2.x + a3.x);
        acc.y = (a0.y + a1.y) + (a2.y + a3.y);
        acc.z = (a0.z + a1.z) + (a2.z + a3.z);
        acc.w = (a0.w + a1.w) + (a2.w + a3.w);

        float dc = g_dis[c];
        float sc = dc * dc;
        float4 hc = *(const float4*)(src + (size_t)c * D + lane * 4);
        float4 r4;
        r4.x = fmaf(acc.x, dc, hc.x * sc);
        r4.y = fmaf(acc.y, dc, hc.y * sc);
        r4.z = fmaf(acc.z, dc, hc.z * sc);
        r4.w = fmaf(acc.w, dc, hc.w * sc);

        __nv_bfloat16 hh[4], ll[4];
        split_bf16(r4.x, hh[0], ll[0]);
        split_bf16(r4.y, hh[1], ll[1]);
        split_bf16(r4.z, hh[2], ll[2]);
        split_bf16(r4.w, hh[3], ll[3]);
        *(uint2*)(outHi + (size_t)c * D + lane * 4) = *(uint2*)hh;
        *(uint2*)(outLo + (size_t)c * D + lane * 4) = *(uint2*)ll;
    }
}

// ---------------- 5: W transpose + bf16 hi/lo split (both layers) --------
__global__ void k_prepW(const float* __restrict__ W1,
                        const float* __restrict__ W2) {
    int i = blockIdx.x * blockDim.x + threadIdx.x;   // 16384
    if (i >= D * D) return;
    int k = i >> 7, nn = i & 127;
    __nv_bfloat16 h, l;
    split_bf16(W1[i], h, l);
    g_WThi1[nn * D + k] = h;
    g_WTlo1[nn * D + k] = l;
    split_bf16(W2[i], h, l);
    g_WThi2[nn * D + k] = h;
    g_WTlo2[nn * D + k] = l;
}

// ---------------- 6/8: bf16 mma GEMM (R4 structure) + bias + ReLU --------
#define WSTRIDE 136
#define ASTRIDE 56
#define SM_WHI 0
#define SM_WLO 34816
#define SM_AHI 69632
#define SM_ALO 83968
#define GEMM_SMEM 98304

__global__ void __launch_bounds__(256, 1)
k_gemm_mma(const __nv_bfloat16* __restrict__ Ahi,
           const __nv_bfloat16* __restrict__ Alo,
           const __nv_bfloat16* __restrict__ Whi,
           const __nv_bfloat16* __restrict__ Wlo,
           const float* __restrict__ bias,
           float* __restrict__ C, int n) {
    extern __shared__ __align__(16) char sm[];
    uint32_t sb = smem_u32(sm);
    int t = threadIdx.x, lane = t & 31, wid = t >> 5;
    int r0 = blockIdx.x * 128;
    int wm = (wid >> 1) * 32;
    int wn = (wid & 1) * 64;

    {
        int row = t >> 1, half = t & 1;
        const uint4* gh = (const uint4*)(Whi + row * D + half * 64);
        const uint4* gl = (const uint4*)(Wlo + row * D + half * 64);
        uint4* shh = (uint4*)(sm + SM_WHI + (row * WSTRIDE + half * 64) * 2);
        uint4* shl = (uint4*)(sm + SM_WLO + (row * WSTRIDE + half * 64) * 2);
        #pragma unroll
        for (int j = 0; j < 8; ++j) { shh[j] = gh[j]; shl[j] = gl[j]; }
    }

    int qa = lane >> 3, la = lane & 7;
    int ra = (qa & 1) * 8 + la;
    int ka = (qa >> 1) * 8;
    int nb = (qa >> 1) * 8 + la;
    int kb = (qa & 1) * 8;

    uint32_t aHiB = sb + SM_AHI + ((wm + ra) * ASTRIDE + ka) * 2;
    uint32_t aLoB = sb + SM_ALO + ((wm + ra) * ASTRIDE + ka) * 2;
    uint32_t bHiB = sb + SM_WHI + ((wn + nb) * WSTRIDE + kb) * 2;
    uint32_t bLoB = sb + SM_WLO + ((wn + nb) * WSTRIDE + kb) * 2;

    float acc[2][8][4];
    #pragma unroll
    for (int mt = 0; mt < 2; ++mt)
        #pragma unroll
        for (int nt = 0; nt < 8; ++nt)
            #pragma unroll
            for (int q = 0; q < 4; ++q) acc[mt][nt][q] = 0.f;

    int arow = t >> 1, apart = t & 1;
    int arg = r0 + arow; if (arg >= n) arg = n - 1;
    const uint4* gAh = (const uint4*)(Ahi + (size_t)arg * D + apart * 16);
    const uint4* gAl = (const uint4*)(Alo + (size_t)arg * D + apart * 16);
    uint4* sAh = (uint4*)(sm + SM_AHI + (arow * ASTRIDE + apart * 16) * 2);
    uint4* sAl = (uint4*)(sm + SM_ALO + (arow * ASTRIDE + apart * 16) * 2);

    for (int kc = 0; kc < 4; ++kc) {
        __syncthreads();
        sAh[0] = gAh[kc * 4 + 0]; sAh[1] = gAh[kc * 4 + 1];
        sAl[0] = gAl[kc * 4 + 0]; sAl[1] = gAl[kc * 4 + 1];
        __syncthreads();

        #pragma unroll
        for (int s = 0; s < 2; ++s) {
            uint32_t ah[2][4], al[2][4], bh[8][2], bl[8][2];
            #pragma unroll
            for (int mt = 0; mt < 2; ++mt) {
                uint32_t ao = (uint32_t)(mt * 16 * ASTRIDE * 2 + s * 32);
                LDSM4(ah[mt][0], ah[mt][1], ah[mt][2], ah[mt][3], aHiB + ao);
                LDSM4(al[mt][0], al[mt][1], al[mt][2], al[mt][3], aLoB + ao);
            }
            #pragma unroll
            for (int p = 0; p < 4; ++p) {
                uint32_t bo = (uint32_t)(p * 16 * WSTRIDE * 2 + (kc * 32 + s * 16) * 2);
                LDSM4(bh[2*p][0], bh[2*p][1], bh[2*p+1][0], bh[2*p+1][1], bHiB + bo);
                LDSM4(bl[2*p][0], bl[2*p][1], bl[2*p+1][0], bl[2*p+1][1], bLoB + bo);
            }
            #pragma unroll
            for (int mt = 0; mt < 2; ++mt)
                #pragma unroll
                for (int nt = 0; nt < 8; ++nt) {
                    MMA_BF16(acc[mt][nt], ah[mt], bh[nt]);
                    MMA_BF16(acc[mt][nt], al[mt], bh[nt]);
                    MMA_BF16(acc[mt][nt], ah[mt], bl[nt]);
                }
        }
    }

    // epilogue: + bias, ReLU, store fp32
    int tr = lane >> 2, tc = (lane & 3) * 2;
    #pragma unroll
    for (int mt = 0; mt < 2; ++mt)
        #pragma unroll
        for (int nt = 0; nt < 8; ++nt) {
            int row = r0 + wm + mt * 16 + tr;
            int col = wn + nt * 8 + tc;
            float2 bv = *(const float2*)(bias + col);
            float v0 = fmaxf(acc[mt][nt][0] + bv.x, 0.f);
            float v1 = fmaxf(acc[mt][nt][1] + bv.y, 0.f);
            float v2 = fmaxf(acc[mt][nt][2] + bv.x, 0.f);
            float v3 = fmaxf(acc[mt][nt][3] + bv.y, 0.f);
            if (row < n)
                *(float2*)(C + (size_t)row * D + col) = make_float2(v0, v1);
            if (row + 8 < n)
                *(float2*)(C + (size_t)(row + 8) * D + col) = make_float2(v2, v3);
        }
}

// ---------------- 9: BN statistics ----------------
__global__ void __launch_bounds__(128) k_stats(const float* __restrict__ h, int n) {
    int d = threadIdx.x;
    float s = 0.f, ss = 0.f;
    for (int r = blockIdx.x; r < n; r += gridDim.x) {
        float v = h[(size_t)r * D + d];
        s += v; ss += v * v;
    }
    atomicAdd(&g_sum[d], s);
    atomicAdd(&g_sumsq[d], ss);
}

// ---------------- 10: BatchNorm apply ----------------
__global__ void k_bn(const float* __restrict__ h,
                     const float* __restrict__ gamma,
                     const float* __restrict__ beta,
                     float* __restrict__ out, int n) {
    int idx = blockIdx.x * blockDim.x + threadIdx.x;
    int total = n * (D / 4);
    if (idx >= total) return;
    int d0 = (idx & 31) * 4;
    float invN = 1.0f / (float)n;
    float4 v = ((const float4*)h)[idx];
    float vv[4] = {v.x, v.y, v.z, v.w};
    float res[4];
    #pragma unroll
    for (int s = 0; s < 4; ++s) {
        int d = d0 + s;
        float m   = g_sum[d] * invN;
        float var = g_sumsq[d] * invN - m * m;
        float inv = rsqrtf(var + EPSV);
        res[s] = gamma[d] * (vv[s] - m) * inv + beta[d];
    }
    ((float4*)out)[idx] = make_float4(res[0], res[1], res[2], res[3]);
}

// ---------------- 11: cleanup — restore zeros for next replay ------------
__global__ void k_cleanup(int n) {
    int i = blockIdx.x * blockDim.x + threadIdx.x;
    if (i < n) { g_cnt[i] = 0; g_cur[i] = 0; }
    if (i < D) { g_sum[i] = 0.f; g_sumsq[i] = 0.f; }
}

// ---------------- launch ----------------
extern "C" void kernel_launch(void* const* d_in, const int* in_sizes, int n_in,
                              void* d_out, int out_size) {
    const float* x     = (const float*)d_in[0];
    const int*   ei    = (const int*)d_in[1];
    const float* W1    = (const float*)d_in[2];
    const float* b1    = (const float*)d_in[3];
    const float* W2    = (const float*)d_in[4];
    const float* b2    = (const float*)d_in[5];
    const float* gamma = (const float*)d_in[6];
    const float* beta  = (const float*)d_in[7];
    float* out = (float*)d_out;

    int n = in_sizes[0] / D;
    int e = in_sizes[1] / 2;
    const int* rows = ei;
    const int* cols = ei + e;

    float* bufO;
    __nv_bfloat16 *yhi, *ylo, *wh1, *wl1, *wh2, *wl2;
    cudaGetSymbolAddress((void**)&bufO, g_out);
    cudaGetSymbolAddress((void**)&yhi, g_Yhi);
    cudaGetSymbolAddress((void**)&ylo, g_Ylo);
    cudaGetSymbolAddress((void**)&wh1, g_WThi1);
    cudaGetSymbolAddress((void**)&wl1, g_WTlo1);
    cudaGetSymbolAddress((void**)&wh2, g_WThi2);
    cudaGetSymbolAddress((void**)&wl2, g_WTlo2);

    cudaFuncSetAttribute(k_gemm_mma, cudaFuncAttributeMaxDynamicSharedMemorySize,
                         GEMM_SMEM);

    int tb = 256;
    int nb_n  = (n + tb - 1) / tb;
    int nb_e  = (e + tb - 1) / tb;
    int nb_f4 = (n * (D / 4) + tb - 1) / tb;
    int gemm_grid = (n + 127) / 128;
    int agg_grid = 2048;

    // 1-3: CSR build (g_cnt/g_cur arrive zeroed; cleanup restores them)
    k_deg<<<nb_e, tb>>>(cols, e);
    k_scanall<<<1, 1024>>>(n);
    k_scatter<<<nb_e, tb>>>(rows, cols, e);
    // 4: layer-1 aggregation on raw x   (<-- profiler capture slot)
    k_agg<<<agg_grid, 256>>>(x, yhi, ylo, n);
    // 5: weight prep
    k_prepW<<<(D * D + tb - 1) / tb, tb>>>(W1, W2);
    // 6: layer-1 GEMM + bias + ReLU
    k_gemm_mma<<<gemm_grid, 256, GEMM_SMEM>>>(yhi, ylo, wh1, wl1, b1, bufO, n);
    // 7: layer-2 aggregation
    k_agg<<<agg_grid, 256>>>(bufO, yhi, ylo, n);
    // 8: layer-2 GEMM + bias + ReLU
    k_gemm_mma<<<gemm_grid, 256, GEMM_SMEM>>>(yhi, ylo, wh2, wl2, b2, bufO, n);
    // 9: BN stats
    k_stats<<<512, 128>>>(bufO, n);
    // 10: BN apply
    k_bn<<<nb_f4, tb>>>(bufO, gamma, beta, out, n);
    // 11: restore zeros for next replay
    k_cleanup<<<nb_n, tb>>>(n);
}

// round 9
// speedup vs baseline: 1.5871x; 1.4639x over previous
#include <cuda_runtime.h>
#include <cuda_bf16.h>
#include <cstdint>

#define D 128
#define MAXN 50000
#define MAXE 600000
#define EPSV 1e-5f

// ---------------- scratch (zero-init at load; k_cleanup restores) --------
__device__ int   g_cnt[MAXN];     // degree histogram
__device__ int   g_cur[MAXN];     // scatter cursor
__device__ int   g_start[MAXN];
__device__ int   g_bsum[256];
__device__ float g_dis[MAXN];
__device__ int2  g_edge[MAXE];    // packed {row, dis[row] bits}
__device__ float g_out[(size_t)MAXN * D];
__device__ __nv_bfloat16 g_Yhi[(size_t)MAXN * D];
__device__ __nv_bfloat16 g_Ylo[(size_t)MAXN * D];
__device__ __nv_bfloat16 g_WThi1[D * D];
__device__ __nv_bfloat16 g_WTlo1[D * D];
__device__ __nv_bfloat16 g_WThi2[D * D];
__device__ __nv_bfloat16 g_WTlo2[D * D];
__device__ float g_sum[D];
__device__ float g_sumsq[D];

// ---------------- helpers ----------------
__device__ __forceinline__ uint32_t smem_u32(const void* p) {
    uint32_t a;
    asm("{ .reg .u64 t; cvta.to.shared.u64 t, %1; cvt.u32.u64 %0, t; }"
        : "=r"(a) : "l"(p));
    return a;
}

#define LDSM4(r0, r1, r2, r3, addr) \
    asm volatile("ldmatrix.sync.aligned.m8n8.x4.shared.b16 {%0,%1,%2,%3}, [%4];" \
        : "=r"(r0), "=r"(r1), "=r"(r2), "=r"(r3) : "r"(addr))

#define MMA_BF16(d, a, b) \
    asm volatile("mma.sync.aligned.m16n8k16.row.col.f32.bf16.bf16.f32 " \
        "{%0,%1,%2,%3}, {%4,%5,%6,%7}, {%8,%9}, {%0,%1,%2,%3};" \
        : "+f"((d)[0]), "+f"((d)[1]), "+f"((d)[2]), "+f"((d)[3]) \
        : "r"((a)[0]), "r"((a)[1]), "r"((a)[2]), "r"((a)[3]), \
          "r"((b)[0]), "r"((b)[1]))

__device__ __forceinline__ void split_bf16(float v, __nv_bfloat16& h, __nv_bfloat16& l) {
    h = __float2bfloat16_rn(v);
    l = __float2bfloat16_rn(v - __bfloat162float(h));
}

// ---------------- 1: W transpose + bf16 hi/lo split ----------------------
__global__ void k_prepW(const float* __restrict__ W1,
                        const float* __restrict__ W2) {
    int i = blockIdx.x * blockDim.x + threadIdx.x;
    if (i >= D * D) return;
    int k = i >> 7, nn = i & 127;
    __nv_bfloat16 h, l;
    split_bf16(W1[i], h, l);
    g_WThi1[nn * D + k] = h;
    g_WTlo1[nn * D + k] = l;
    split_bf16(W2[i], h, l);
    g_WThi2[nn * D + k] = h;
    g_WTlo2[nn * D + k] = l;
}

// ---------------- 2: degree histogram ------------------------------------
__global__ void k_deg(const int* __restrict__ cols, int e) {
    int i = blockIdx.x * blockDim.x + threadIdx.x;
    if (i < e) atomicAdd(&g_cnt[cols[i]], 1);
}

// ---------------- 3: per-block exclusive scan ----------------------------
__global__ void __launch_bounds__(256) k_scan1(int n) {
    __shared__ int sh[256];
    int t = threadIdx.x;
    int i = blockIdx.x * 256 + t;
    int v = (i < n) ? g_cnt[i] : 0;
    sh[t] = v;
    __syncthreads();
    #pragma unroll
    for (int off = 1; off < 256; off <<= 1) {
        int u = (t >= off) ? sh[t - off] : 0;
        __syncthreads();
        sh[t] += u;
        __syncthreads();
    }
    if (i < n) g_start[i] = sh[t] - v;
    if (t == 255) g_bsum[blockIdx.x] = sh[255];
}

// ---------------- 4: block-offset add (parallel reduce per block) + dis --
__global__ void __launch_bounds__(256) k_scanF(int n, int nb) {
    __shared__ int red[256];
    int t = threadIdx.x;
    int b = blockIdx.x;
    red[t] = (t < b && t < nb) ? g_bsum[t] : 0;
    __syncthreads();
    #pragma unroll
    for (int off = 128; off > 0; off >>= 1) {
        if (t < off) red[t] += red[t + off];
        __syncthreads();
    }
    int offset = red[0];
    int i = b * 256 + t;
    if (i < n) {
        g_start[i] += offset;
        g_dis[i] = rsqrtf((float)g_cnt[i] + 1.0f);   // +1 self loop
    }
}

// ---------------- 5: CSR scatter, packed (row, dis[row]) -----------------
__global__ void k_scatter(const int* __restrict__ rows,
                          const int* __restrict__ cols, int e) {
    int i = blockIdx.x * blockDim.x + threadIdx.x;
    if (i < e) {
        int r = rows[i];
        int c = cols[i];
        int p = g_start[c] + atomicAdd(&g_cur[c], 1);
        g_edge[p] = make_int2(r, __float_as_int(g_dis[r]));
    }
}

// ---------------- 6/8: aggregation Y = A_hat * src, 8-deep MLP -----------
__global__ void __launch_bounds__(256) k_agg(const float* __restrict__ src,
                                             __nv_bfloat16* __restrict__ outHi,
                                             __nv_bfloat16* __restrict__ outLo,
                                             int n) {
    int tid  = threadIdx.x;
    int lane = tid & 31;
    int wid  = tid >> 5;

    for (int c = blockIdx.x * 8 + wid; c < n; c += gridDim.x * 8) {
        int s0  = g_start[c];
        int end = s0 + g_cnt[c];
        float4 a0 = make_float4(0.f, 0.f, 0.f, 0.f);
        float4 a1 = a0, a2 = a0, a3 = a0;

        int j = s0;
        for (; j + 8 <= end; j += 8) {
            int2 e0 = __ldg(&g_edge[j + 0]);
            int2 e1 = __ldg(&g_edge[j + 1]);
            int2 e2 = __ldg(&g_edge[j + 2]);
            int2 e3 = __ldg(&g_edge[j + 3]);
            int2 e4 = __ldg(&g_edge[j + 4]);
            int2 e5 = __ldg(&g_edge[j + 5]);
            int2 e6 = __ldg(&g_edge[j + 6]);
            int2 e7 = __ldg(&g_edge[j + 7]);
            float4 v0 = *(const float4*)(src + (size_t)e0.x * D + lane * 4);
            float4 v1 = *(const float4*)(src + (size_t)e1.x * D + lane * 4);
            float4 v2 = *(const float4*)(src + (size_t)e2.x * D + lane * 4);
            float4 v3 = *(const float4*)(src + (size_t)e3.x * D + lane * 4);
            float4 v4 = *(const float4*)(src + (size_t)e4.x * D + lane * 4);
            float4 v5 = *(const float4*)(src + (size_t)e5.x * D + lane * 4);
            float4 v6 = *(const float4*)(src + (size_t)e6.x * D + lane * 4);
            float4 v7 = *(const float4*)(src + (size_t)e7.x * D + lane * 4);
            float d0 = __int_as_float(e0.y), d1 = __int_as_float(e1.y);
            float d2 = __int_as_float(e2.y), d3 = __int_as_float(e3.y);
            float d4 = __int_as_float(e4.y), d5 = __int_as_float(e5.y);
            float d6 = __int_as_float(e6.y), d7 = __int_as_float(e7.y);
            a0.x = fmaf(v0.x, d0, a0.x); a0.y = fmaf(v0.y, d0, a0.y);
            a0.z = fmaf(v0.z, d0, a0.z); a0.w = fmaf(v0.w, d0, a0.w);
            a1.x = fmaf(v1.x, d1, a1.x); a1.y = fmaf(v1.y, d1, a1.y);
            a1.z = fmaf(v1.z, d1, a1.z); a1.w = fmaf(v1.w, d1, a1.w);
            a2.x = fmaf(v2.x, d2, a2.x); a2.y = fmaf(v2.y, d2, a2.y);
            a2.z = fmaf(v2.z, d2, a2.z); a2.w = fmaf(v2.w, d2, a2.w);
            a3.x = fmaf(v3.x, d3, a3.x); a3.y = fmaf(v3.y, d3, a3.y);
            a3.z = fmaf(v3.z, d3, a3.z); a3.w = fmaf(v3.w, d3, a3.w);
            a0.x = fmaf(v4.x, d4, a0.x); a0.y = fmaf(v4.y, d4, a0.y);
            a0.z = fmaf(v4.z, d4, a0.z); a0.w = fmaf(v4.w, d4, a0.w);
            a1.x = fmaf(v5.x, d5, a1.x); a1.y = fmaf(v5.y, d5, a1.y);
            a1.z = fmaf(v5.z, d5, a1.z); a1.w = fmaf(v5.w, d5, a1.w);
            a2.x = fmaf(v6.x, d6, a2.x); a2.y = fmaf(v6.y, d6, a2.y);
            a2.z = fmaf(v6.z, d6, a2.z); a2.w = fmaf(v6.w, d6, a2.w);
            a3.x = fmaf(v7.x, d7, a3.x); a3.y = fmaf(v7.y, d7, a3.y);
            a3.z = fmaf(v7.z, d7, a3.z); a3.w = fmaf(v7.w, d7, a3.w);
        }
        for (; j < end; ++j) {
            int2 ee = __ldg(&g_edge[j]);
            float dr = __int_as_float(ee.y);
            float4 v = *(const float4*)(src + (size_t)ee.x * D + lane * 4);
            a0.x = fmaf(v.x, dr, a0.x); a0.y = fmaf(v.y, dr, a0.y);
            a0.z = fmaf(v.z, dr, a0.z); a0.w = fmaf(v.w, dr, a0.w);
        }
        float4 acc;
        acc.x = (a0.x + a1.x) + (a2.x + a3.x);
        acc.y = (a0.y + a1.y) + (a2.y + a3.y);
        acc.z = (a0.z + a1.z) + (a2.z + a3.z);
        acc.w = (a0.w + a1.w) + (a2.w + a3.w);

        float dc = g_dis[c];
        float sc = dc * dc;
        float4 hc = *(const float4*)(src + (size_t)c * D + lane * 4);
        float4 r4;
        r4.x = fmaf(acc.x, dc, hc.x * sc);
        r4.y = fmaf(acc.y, dc, hc.y * sc);
        r4.z = fmaf(acc.z, dc, hc.z * sc);
        r4.w = fmaf(acc.w, dc, hc.w * sc);

        __nv_bfloat16 hh[4], ll[4];
        split_bf16(r4.x, hh[0], ll[0]);
        split_bf16(r4.y, hh[1], ll[1]);
        split_bf16(r4.z, hh[2], ll[2]);
        split_bf16(r4.w, hh[3], ll[3]);
        *(uint2*)(outHi + (size_t)c * D + lane * 4) = *(uint2*)hh;
        *(uint2*)(outLo + (size_t)c * D + lane * 4) = *(uint2*)ll;
    }
}

// ---------------- 7/9: bf16 mma GEMM, A double-buffered ------------------
#define WSTRIDE 136
#define ABSTRIDE 40    // bf16 units/row of a 32-wide A chunk (80B, conflict-free)
#define SM_WHI 0
#define SM_WLO 34816
#define SM_A   69632   // 4 x 10240: buf0{hi,lo}, buf1{hi,lo}
#define ABUF(buf, dt) (SM_A + (buf) * 20480 + (dt) * 10240)
#define GEMM_SMEM 110592

__global__ void __launch_bounds__(256, 1)
k_gemm_mma(const __nv_bfloat16* __restrict__ Ahi,
           const __nv_bfloat16* __restrict__ Alo,
           const __nv_bfloat16* __restrict__ Whi,
           const __nv_bfloat16* __restrict__ Wlo,
           const float* __restrict__ bias,
           float* __restrict__ C, int n) {
    extern __shared__ __align__(16) char sm[];
    uint32_t sb = smem_u32(sm);
    int t = threadIdx.x, lane = t & 31, wid = t >> 5;
    int r0 = blockIdx.x * 128;
    int wm = (wid >> 1) * 32;
    int wn = (wid & 1) * 64;

    // stage W hi/lo [128][128]
    {
        int row = t >> 1, half = t & 1;
        const uint4* gh = (const uint4*)(Whi + row * D + half * 64);
        const uint4* gl = (const uint4*)(Wlo + row * D + half * 64);
        uint4* shh = (uint4*)(sm + SM_WHI + (row * WSTRIDE + half * 64) * 2);
        uint4* shl = (uint4*)(sm + SM_WLO + (row * WSTRIDE + half * 64) * 2);
        #pragma unroll
        for (int j = 0; j < 8; ++j) { shh[j] = gh[j]; shl[j] = gl[j]; }
    }

    int qa = lane >> 3, la = lane & 7;
    int ra = (qa & 1) * 8 + la;
    int ka = (qa >> 1) * 8;
    int nb = (qa >> 1) * 8 + la;
    int kb = (qa & 1) * 8;

    uint32_t aHiBase[2], aLoBase[2];
    #pragma unroll
    for (int bf = 0; bf < 2; ++bf) {
        aHiBase[bf] = sb + ABUF(bf, 0) + ((wm + ra) * ABSTRIDE + ka) * 2;
        aLoBase[bf] = sb + ABUF(bf, 1) + ((wm + ra) * ABSTRIDE + ka) * 2;
    }
    uint32_t bHiB = sb + SM_WHI + ((wn + nb) * WSTRIDE + kb) * 2;
    uint32_t bLoB = sb + SM_WLO + ((wn + nb) * WSTRIDE + kb) * 2;

    float acc[2][8][4];
    #pragma unroll
    for (int mt = 0; mt < 2; ++mt)
        #pragma unroll
        for (int nt = 0; nt < 8; ++nt)
            #pragma unroll
            for (int q = 0; q < 4; ++q) acc[mt][nt][q] = 0.f;

    int arow = t >> 1, apart = t & 1;
    int arg = r0 + arow; if (arg >= n) arg = n - 1;
    const uint4* gAh = (const uint4*)(Ahi + (size_t)arg * D);
    const uint4* gAl = (const uint4*)(Alo + (size_t)arg * D);
    int gidx = apart * 2;                 // uint4 index within 32-elem chunk
    uint32_t sOff = (uint32_t)((arow * ABSTRIDE + apart * 16) * 2);

    // prologue: stage chunk 0 into buf 0
    {
        uint4 h0 = gAh[gidx], h1 = gAh[gidx + 1];
        uint4 l0 = gAl[gidx], l1 = gAl[gidx + 1];
        *(uint4*)(sm + ABUF(0, 0) + sOff)      = h0;
        *(uint4*)(sm + ABUF(0, 0) + sOff + 16) = h1;
        *(uint4*)(sm + ABUF(0, 1) + sOff)      = l0;
        *(uint4*)(sm + ABUF(0, 1) + sOff + 16) = l1;
    }
    __syncthreads();

    #pragma unroll
    for (int kc = 0; kc < 4; ++kc) {
        int cur = kc & 1, nxt = cur ^ 1;
        // prefetch next A chunk into regs (latency hidden behind MMAs)
        uint4 ph0, ph1, pl0, pl1;
        if (kc < 3) {
            ph0 = gAh[(kc + 1) * 4 + gidx]; ph1 = gAh[(kc + 1) * 4 + gidx + 1];
            pl0 = gAl[(kc + 1) * 4 + gidx]; pl1 = gAl[(kc + 1) * 4 + gidx + 1];
        }
        #pragma unroll
        for (int s = 0; s < 2; ++s) {
            uint32_t ah[2][4], al[2][4], bh[8][2], bl[8][2];
            #pragma unroll
            for (int mt = 0; mt < 2; ++mt) {
                uint32_t ao = (uint32_t)(mt * 16 * ABSTRIDE * 2 + s * 32);
                LDSM4(ah[mt][0], ah[mt][1], ah[mt][2], ah[mt][3], aHiBase[cur] + ao);
                LDSM4(al[mt][0], al[mt][1], al[mt][2], al[mt][3], aLoBase[cur] + ao);
            }
            #pragma unroll
            for (int p = 0; p < 4; ++p) {
                uint32_t bo = (uint32_t)(p * 16 * WSTRIDE * 2 + (kc * 32 + s * 16) * 2);
                LDSM4(bh[2*p][0], bh[2*p][1], bh[2*p+1][0], bh[2*p+1][1], bHiB + bo);
                LDSM4(bl[2*p][0], bl[2*p][1], bl[2*p+1][0], bl[2*p+1][1], bLoB + bo);
            }
            #pragma unroll
            for (int mt = 0; mt < 2; ++mt)
                #pragma unroll
                for (int nt = 0; nt < 8; ++nt) {
                    MMA_BF16(acc[mt][nt], ah[mt], bh[nt]);
                    MMA_BF16(acc[mt][nt], al[mt], bh[nt]);
                    MMA_BF16(acc[mt][nt], ah[mt], bl[nt]);
                }
        }
        if (kc < 3) {
            *(uint4*)(sm + ABUF(nxt, 0) + sOff)      = ph0;
            *(uint4*)(sm + ABUF(nxt, 0) + sOff + 16) = ph1;
            *(uint4*)(sm + ABUF(nxt, 1) + sOff)      = pl0;
            *(uint4*)(sm + ABUF(nxt, 1) + sOff + 16) = pl1;
            __syncthreads();
        }
    }

    // epilogue: + bias, ReLU, store fp32
    int tr = lane >> 2, tc = (lane & 3) * 2;
    #pragma unroll
    for (int mt = 0; mt < 2; ++mt)
        #pragma unroll
        for (int nt = 0; nt < 8; ++nt) {
            int row = r0 + wm + mt * 16 + tr;
            int col = wn + nt * 8 + tc;
            float2 bv = *(const float2*)(bias + col);
            float v0 = fmaxf(acc[mt][nt][0] + bv.x, 0.f);
            float v1 = fmaxf(acc[mt][nt][1] + bv.y, 0.f);
            float v2 = fmaxf(acc[mt][nt][2] + bv.x, 0.f);
            float v3 = fmaxf(acc[mt][nt][3] + bv.y, 0.f);
            if (row < n)
                *(float2*)(C + (size_t)row * D + col) = make_float2(v0, v1);
            if (row + 8 < n)
                *(float2*)(C + (size_t)(row + 8) * D + col) = make_float2(v2, v3);
        }
}

// ---------------- 10: BN statistics ----------------
__global__ void __launch_bounds__(128) k_stats(const float* __restrict__ h, int n) {
    int d = threadIdx.x;
    float s = 0.f, ss = 0.f;
    for (int r = blockIdx.x; r < n; r += gridDim.x) {
        float v = h[(size_t)r * D + d];
        s += v; ss += v * v;
    }
    atomicAdd(&g_sum[d], s);
    atomicAdd(&g_sumsq[d], ss);
}

// ---------------- 11: BatchNorm apply ----------------
__global__ void k_bn(const float* __restrict__ h,
                     const float* __restrict__ gamma,
                     const float* __restrict__ beta,
                     float* __restrict__ out, int n) {
    int idx = blockIdx.x * blockDim.x + threadIdx.x;
    int total = n * (D / 4);
    if (idx >= total) return;
    int d0 = (idx & 31) * 4;
    float invN = 1.0f / (float)n;
    float4 v = ((const float4*)h)[idx];
    float vv[4] = {v.x, v.y, v.z, v.w};
    float res[4];
    #pragma unroll
    for (int s = 0; s < 4; ++s) {
        int d = d0 + s;
        float m   = g_sum[d] * invN;
        float var = g_sumsq[d] * invN - m * m;
        float inv = rsqrtf(var + EPSV);
        res[s] = gamma[d] * (vv[s] - m) * inv + beta[d];
    }
    ((float4*)out)[idx] = make_float4(res[0], res[1], res[2], res[3]);
}

// ---------------- 12: cleanup — restore zeros for next replay ------------
__global__ void k_cleanup(int n) {
    int i = blockIdx.x * blockDim.x + threadIdx.x;
    if (i < n) { g_cnt[i] = 0; g_cur[i] = 0; }
    if (i < D) { g_sum[i] = 0.f; g_sumsq[i] = 0.f; }
}

// ---------------- launch ----------------
extern "C" void kernel_launch(void* const* d_in, const int* in_sizes, int n_in,
                              void* d_out, int out_size) {
    const float* x     = (const float*)d_in[0];
    const int*   ei    = (const int*)d_in[1];
    const float* W1    = (const float*)d_in[2];
    const float* b1    = (const float*)d_in[3];
    const float* W2    = (const float*)d_in[4];
    const float* b2    = (const float*)d_in[5];
    const float* gamma = (const float*)d_in[6];
    const float* beta  = (const float*)d_in[7];
    float* out = (float*)d_out;

    int n = in_sizes[0] / D;
    int e = in_sizes[1] / 2;
    const int* rows = ei;
    const int* cols = ei + e;

    float* bufO;
    __nv_bfloat16 *yhi, *ylo, *wh1, *wl1, *wh2, *wl2;
    cudaGetSymbolAddress((void**)&bufO, g_out);
    cudaGetSymbolAddress((void**)&yhi, g_Yhi);
    cudaGetSymbolAddress((void**)&ylo, g_Ylo);
    cudaGetSymbolAddress((void**)&wh1, g_WThi1);
    cudaGetSymbolAddress((void**)&wl1, g_WTlo1);
    cudaGetSymbolAddress((void**)&wh2, g_WThi2);
    cudaGetSymbolAddress((void**)&wl2, g_WTlo2);

    cudaFuncSetAttribute(k_gemm_mma, cudaFuncAttributeMaxDynamicSharedMemorySize,
                         GEMM_SMEM);

    int tb = 256;
    int nb_n  = (n + tb - 1) / tb;          // 196
    int nb_e  = (e + tb - 1) / tb;
    int nb_f4 = (n * (D / 4) + tb - 1) / tb;
    int gemm_grid = (n + 127) / 128;
    int agg_grid = 2048;

    // CSR build (parallel scan)
    k_prepW<<<(D * D + tb - 1) / tb, tb>>>(W1, W2);
    k_deg<<<nb_e, tb>>>(cols, e);
    k_scan1<<<nb_n, 256>>>(n);
    k_scanF<<<nb_n, 256>>>(n, nb_n);
    k_scatter<<<nb_e, tb>>>(rows, cols, e);

    // layer 1
    k_agg<<<agg_grid, 256>>>(x, yhi, ylo, n);
    k_gemm_mma<<<gemm_grid, 256, GEMM_SMEM>>>(yhi, ylo, wh1, wl1, b1, bufO, n);
    // layer 2
    k_agg<<<agg_grid, 256>>>(bufO, yhi, ylo, n);
    k_gemm_mma<<<gemm_grid, 256, GEMM_SMEM>>>(yhi, ylo, wh2, wl2, b2, bufO, n);

    // batchnorm
    k_stats<<<512, 128>>>(bufO, n);
    k_bn<<<nb_f4, tb>>>(bufO, gamma, beta, out, n);
    k_cleanup<<<nb_n, tb>>>(n);
}

// round 10
// speedup vs baseline: 1.8093x; 1.1400x over previous
#include <cuda_runtime.h>
#include <cuda_bf16.h>
#include <cstdint>

#define D 128
#define MAXN 50000
#define MAXE 600000
#define EPSV 1e-5f

// ---------------- scratch (zero-init at load; k_deg/k_bn restore) --------
__device__ int   g_cnt[MAXN];     // degree histogram (zeroed by k_bn)
__device__ int   g_cur[MAXN];     // scatter cursor   (zeroed by k_bn)
__device__ int   g_start[MAXN];
__device__ int   g_bsum[256];
__device__ float g_dis[MAXN];
__device__ int2  g_edge[MAXE];    // packed {row, dis[row] bits}
__device__ float g_out[(size_t)MAXN * D];
__device__ __nv_bfloat16 g_Yhi[(size_t)MAXN * D];
__device__ __nv_bfloat16 g_Ylo[(size_t)MAXN * D];
__device__ __nv_bfloat16 g_WThi1[D * D];
__device__ __nv_bfloat16 g_WTlo1[D * D];
__device__ __nv_bfloat16 g_WThi2[D * D];
__device__ __nv_bfloat16 g_WTlo2[D * D];
__device__ float g_sum[D];        // zeroed by k_deg each replay
__device__ float g_sumsq[D];

// ---------------- helpers ----------------
__device__ __forceinline__ uint32_t smem_u32(const void* p) {
    uint32_t a;
    asm("{ .reg .u64 t; cvta.to.shared.u64 t, %1; cvt.u32.u64 %0, t; }"
        : "=r"(a) : "l"(p));
    return a;
}

#define LDSM4(r0, r1, r2, r3, addr) \
    asm volatile("ldmatrix.sync.aligned.m8n8.x4.shared.b16 {%0,%1,%2,%3}, [%4];" \
        : "=r"(r0), "=r"(r1), "=r"(r2), "=r"(r3) : "r"(addr))

#define MMA_BF16(d, a, b) \
    asm volatile("mma.sync.aligned.m16n8k16.row.col.f32.bf16.bf16.f32 " \
        "{%0,%1,%2,%3}, {%4,%5,%6,%7}, {%8,%9}, {%0,%1,%2,%3};" \
        : "+f"((d)[0]), "+f"((d)[1]), "+f"((d)[2]), "+f"((d)[3]) \
        : "r"((a)[0]), "r"((a)[1]), "r"((a)[2]), "r"((a)[3]), \
          "r"((b)[0]), "r"((b)[1]))

__device__ __forceinline__ void split_bf16(float v, __nv_bfloat16& h, __nv_bfloat16& l) {
    h = __float2bfloat16_rn(v);
    l = __float2bfloat16_rn(v - __bfloat162float(h));
}

// ---------------- 1: degree histogram + stats zero -----------------------
__global__ void k_deg(const int* __restrict__ cols, int e) {
    int i = blockIdx.x * blockDim.x + threadIdx.x;
    if (i < e) atomicAdd(&g_cnt[cols[i]], 1);
    if (i < D) { g_sum[i] = 0.f; g_sumsq[i] = 0.f; }
}

// ---------------- 2: per-block scan + W split (fused) --------------------
__global__ void __launch_bounds__(256) k_scan1(const float* __restrict__ W1,
                                               const float* __restrict__ W2,
                                               int n) {
    __shared__ int sh[256];
    int t = threadIdx.x;
    int i = blockIdx.x * 256 + t;

    // side job: W transpose + bf16 hi/lo split (first 64 blocks)
    if (i < D * D) {
        int k = i >> 7, nn = i & 127;
        __nv_bfloat16 h, l;
        split_bf16(W1[i], h, l);
        g_WThi1[nn * D + k] = h;
        g_WTlo1[nn * D + k] = l;
        split_bf16(W2[i], h, l);
        g_WThi2[nn * D + k] = h;
        g_WTlo2[nn * D + k] = l;
    }

    int v = (i < n) ? g_cnt[i] : 0;
    sh[t] = v;
    __syncthreads();
    #pragma unroll
    for (int off = 1; off < 256; off <<= 1) {
        int u = (t >= off) ? sh[t - off] : 0;
        __syncthreads();
        sh[t] += u;
        __syncthreads();
    }
    if (i < n) g_start[i] = sh[t] - v;
    if (t == 255) g_bsum[blockIdx.x] = sh[255];
}

// ---------------- 3: block-offset add + dis ------------------------------
__global__ void __launch_bounds__(256) k_scanF(int n, int nb) {
    __shared__ int red[256];
    int t = threadIdx.x;
    int b = blockIdx.x;
    red[t] = (t < b && t < nb) ? g_bsum[t] : 0;
    __syncthreads();
    #pragma unroll
    for (int off = 128; off > 0; off >>= 1) {
        if (t < off) red[t] += red[t + off];
        __syncthreads();
    }
    int offset = red[0];
    int i = b * 256 + t;
    if (i < n) {
        g_start[i] += offset;
        g_dis[i] = rsqrtf((float)g_cnt[i] + 1.0f);   // +1 self loop
    }
}

// ---------------- 4: CSR scatter, packed (row, dis[row]) -----------------
__global__ void k_scatter(const int* __restrict__ rows,
                          const int* __restrict__ cols, int e) {
    int i = blockIdx.x * blockDim.x + threadIdx.x;
    if (i < e) {
        int r = rows[i];
        int c = cols[i];
        int p = g_start[c] + atomicAdd(&g_cur[c], 1);
        g_edge[p] = make_int2(r, __float_as_int(g_dis[r]));
    }
}

// ---------------- 5/7: aggregation Y = A_hat * src, 8-deep MLP -----------
__global__ void __launch_bounds__(256) k_agg(const float* __restrict__ src,
                                             __nv_bfloat16* __restrict__ outHi,
                                             __nv_bfloat16* __restrict__ outLo,
                                             int n) {
    int tid  = threadIdx.x;
    int lane = tid & 31;
    int wid  = tid >> 5;

    for (int c = blockIdx.x * 8 + wid; c < n; c += gridDim.x * 8) {
        int s0  = g_start[c];
        int end = s0 + g_cnt[c];
        float4 a0 = make_float4(0.f, 0.f, 0.f, 0.f);
        float4 a1 = a0, a2 = a0, a3 = a0;

        int j = s0;
        for (; j + 8 <= end; j += 8) {
            int2 e0 = __ldg(&g_edge[j + 0]);
            int2 e1 = __ldg(&g_edge[j + 1]);
            int2 e2 = __ldg(&g_edge[j + 2]);
            int2 e3 = __ldg(&g_edge[j + 3]);
            int2 e4 = __ldg(&g_edge[j + 4]);
            int2 e5 = __ldg(&g_edge[j + 5]);
            int2 e6 = __ldg(&g_edge[j + 6]);
            int2 e7 = __ldg(&g_edge[j + 7]);
            float4 v0 = *(const float4*)(src + (size_t)e0.x * D + lane * 4);
            float4 v1 = *(const float4*)(src + (size_t)e1.x * D + lane * 4);
            float4 v2 = *(const float4*)(src + (size_t)e2.x * D + lane * 4);
            float4 v3 = *(const float4*)(src + (size_t)e3.x * D + lane * 4);
            float4 v4 = *(const float4*)(src + (size_t)e4.x * D + lane * 4);
            float4 v5 = *(const float4*)(src + (size_t)e5.x * D + lane * 4);
            float4 v6 = *(const float4*)(src + (size_t)e6.x * D + lane * 4);
            float4 v7 = *(const float4*)(src + (size_t)e7.x * D + lane * 4);
            float d0 = __int_as_float(e0.y), d1 = __int_as_float(e1.y);
            float d2 = __int_as_float(e2.y), d3 = __int_as_float(e3.y);
            float d4 = __int_as_float(e4.y), d5 = __int_as_float(e5.y);
            float d6 = __int_as_float(e6.y), d7 = __int_as_float(e7.y);
            a0.x = fmaf(v0.x, d0, a0.x); a0.y = fmaf(v0.y, d0, a0.y);
            a0.z = fmaf(v0.z, d0, a0.z); a0.w = fmaf(v0.w, d0, a0.w);
            a1.x = fmaf(v1.x, d1, a1.x); a1.y = fmaf(v1.y, d1, a1.y);
            a1.z = fmaf(v1.z, d1, a1.z); a1.w = fmaf(v1.w, d1, a1.w);
            a2.x = fmaf(v2.x, d2, a2.x); a2.y = fmaf(v2.y, d2, a2.y);
            a2.z = fmaf(v2.z, d2, a2.z); a2.w = fmaf(v2.w, d2, a2.w);
            a3.x = fmaf(v3.x, d3, a3.x); a3.y = fmaf(v3.y, d3, a3.y);
            a3.z = fmaf(v3.z, d3, a3.z); a3.w = fmaf(v3.w, d3, a3.w);
            a0.x = fmaf(v4.x, d4, a0.x); a0.y = fmaf(v4.y, d4, a0.y);
            a0.z = fmaf(v4.z, d4, a0.z); a0.w = fmaf(v4.w, d4, a0.w);
            a1.x = fmaf(v5.x, d5, a1.x); a1.y = fmaf(v5.y, d5, a1.y);
            a1.z = fmaf(v5.z, d5, a1.z); a1.w = fmaf(v5.w, d5, a1.w);
            a2.x = fmaf(v6.x, d6, a2.x); a2.y = fmaf(v6.y, d6, a2.y);
            a2.z = fmaf(v6.z, d6, a2.z); a2.w = fmaf(v6.w, d6, a2.w);
            a3.x = fmaf(v7.x, d7, a3.x); a3.y = fmaf(v7.y, d7, a3.y);
            a3.z = fmaf(v7.z, d7, a3.z); a3.w = fmaf(v7.w, d7, a3.w);
        }
        for (; j < end; ++j) {
            int2 ee = __ldg(&g_edge[j]);
            float dr = __int_as_float(ee.y);
            float4 v = *(const float4*)(src + (size_t)ee.x * D + lane * 4);
            a0.x = fmaf(v.x, dr, a0.x); a0.y = fmaf(v.y, dr, a0.y);
            a0.z = fmaf(v.z, dr, a0.z); a0.w = fmaf(v.w, dr, a0.w);
        }
        float4 acc;
        acc.x = (a0.x + a1.x) + (a2.x + a3.x);
        acc.y = (a0.y + a1.y) + (a2.y + a3.y);
        acc.z = (a0.z + a1.z) + (a2.z + a3.z);
        acc.w = (a0.w + a1.w) + (a2.w + a3.w);

        float dc = g_dis[c];
        float sc = dc * dc;
        float4 hc = *(const float4*)(src + (size_t)c * D + lane * 4);
        float4 r4;
        r4.x = fmaf(acc.x, dc, hc.x * sc);
        r4.y = fmaf(acc.y, dc, hc.y * sc);
        r4.z = fmaf(acc.z, dc, hc.z * sc);
        r4.w = fmaf(acc.w, dc, hc.w * sc);

        __nv_bfloat16 hh[4], ll[4];
        split_bf16(r4.x, hh[0], ll[0]);
        split_bf16(r4.y, hh[1], ll[1]);
        split_bf16(r4.z, hh[2], ll[2]);
        split_bf16(r4.w, hh[3], ll[3]);
        *(uint2*)(outHi + (size_t)c * D + lane * 4) = *(uint2*)hh;
        *(uint2*)(outLo + (size_t)c * D + lane * 4) = *(uint2*)ll;
    }
}

// ---------------- 6/8: bf16 mma GEMM, A dbl-buffered, fused BN stats -----
#define WSTRIDE 136
#define ABSTRIDE 40
#define SM_WHI 0
#define SM_WLO 34816
#define SM_A   69632
#define ABUF(buf, dt) (SM_A + (buf) * 20480 + (dt) * 10240)
#define GEMM_SMEM 110592

__global__ void __launch_bounds__(256, 1)
k_gemm_mma(const __nv_bfloat16* __restrict__ Ahi,
           const __nv_bfloat16* __restrict__ Alo,
           const __nv_bfloat16* __restrict__ Whi,
           const __nv_bfloat16* __restrict__ Wlo,
           const float* __restrict__ bias,
           float* __restrict__ C, int n, int do_stats) {
    extern __shared__ __align__(16) char sm[];
    __shared__ float s_stat[2 * D];
    uint32_t sb = smem_u32(sm);
    int t = threadIdx.x, lane = t & 31, wid = t >> 5;
    int r0 = blockIdx.x * 128;
    int wm = (wid >> 1) * 32;
    int wn = (wid & 1) * 64;

    // stage W hi/lo [128][128]
    {
        int row = t >> 1, half = t & 1;
        const uint4* gh = (const uint4*)(Whi + row * D + half * 64);
        const uint4* gl = (const uint4*)(Wlo + row * D + half * 64);
        uint4* shh = (uint4*)(sm + SM_WHI + (row * WSTRIDE + half * 64) * 2);
        uint4* shl = (uint4*)(sm + SM_WLO + (row * WSTRIDE + half * 64) * 2);
        #pragma unroll
        for (int j = 0; j < 8; ++j) { shh[j] = gh[j]; shl[j] = gl[j]; }
    }
    if (do_stats && t < 2 * D) s_stat[t] = 0.f;

    int qa = lane >> 3, la = lane & 7;
    int ra = (qa & 1) * 8 + la;
    int ka = (qa >> 1) * 8;
    int nb = (qa >> 1) * 8 + la;
    int kb = (qa & 1) * 8;

    uint32_t aHiBase[2], aLoBase[2];
    #pragma unroll
    for (int bf = 0; bf < 2; ++bf) {
        aHiBase[bf] = sb + ABUF(bf, 0) + ((wm + ra) * ABSTRIDE + ka) * 2;
        aLoBase[bf] = sb + ABUF(bf, 1) + ((wm + ra) * ABSTRIDE + ka) * 2;
    }
    uint32_t bHiB = sb + SM_WHI + ((wn + nb) * WSTRIDE + kb) * 2;
    uint32_t bLoB = sb + SM_WLO + ((wn + nb) * WSTRIDE + kb) * 2;

    float acc[2][8][4];
    #pragma unroll
    for (int mt = 0; mt < 2; ++mt)
        #pragma unroll
        for (int nt = 0; nt < 8; ++nt)
            #pragma unroll
            for (int q = 0; q < 4; ++q) acc[mt][nt][q] = 0.f;

    int arow = t >> 1, apart = t & 1;
    int arg = r0 + arow; if (arg >= n) arg = n - 1;
    const uint4* gAh = (const uint4*)(Ahi + (size_t)arg * D);
    const uint4* gAl = (const uint4*)(Alo + (size_t)arg * D);
    int gidx = apart * 2;
    uint32_t sOff = (uint32_t)((arow * ABSTRIDE + apart * 16) * 2);

    {
        uint4 h0 = gAh[gidx], h1 = gAh[gidx + 1];
        uint4 l0 = gAl[gidx], l1 = gAl[gidx + 1];
        *(uint4*)(sm + ABUF(0, 0) + sOff)      = h0;
        *(uint4*)(sm + ABUF(0, 0) + sOff + 16) = h1;
        *(uint4*)(sm + ABUF(0, 1) + sOff)      = l0;
        *(uint4*)(sm + ABUF(0, 1) + sOff + 16) = l1;
    }
    __syncthreads();

    #pragma unroll
    for (int kc = 0; kc < 4; ++kc) {
        int cur = kc & 1, nxt = cur ^ 1;
        uint4 ph0, ph1, pl0, pl1;
        if (kc < 3) {
            ph0 = gAh[(kc + 1) * 4 + gidx]; ph1 = gAh[(kc + 1) * 4 + gidx + 1];
            pl0 = gAl[(kc + 1) * 4 + gidx]; pl1 = gAl[(kc + 1) * 4 + gidx + 1];
        }
        #pragma unroll
        for (int s = 0; s < 2; ++s) {
            uint32_t ah[2][4], al[2][4], bh[8][2], bl[8][2];
            #pragma unroll
            for (int mt = 0; mt < 2; ++mt) {
                uint32_t ao = (uint32_t)(mt * 16 * ABSTRIDE * 2 + s * 32);
                LDSM4(ah[mt][0], ah[mt][1], ah[mt][2], ah[mt][3], aHiBase[cur] + ao);
                LDSM4(al[mt][0], al[mt][1], al[mt][2], al[mt][3], aLoBase[cur] + ao);
            }
            #pragma unroll
            for (int p = 0; p < 4; ++p) {
                uint32_t bo = (uint32_t)(p * 16 * WSTRIDE * 2 + (kc * 32 + s * 16) * 2);
                LDSM4(bh[2*p][0], bh[2*p][1], bh[2*p+1][0], bh[2*p+1][1], bHiB + bo);
                LDSM4(bl[2*p][0], bl[2*p][1], bl[2*p+1][0], bl[2*p+1][1], bLoB + bo);
            }
            #pragma unroll
            for (int mt = 0; mt < 2; ++mt)
                #pragma unroll
                for (int nt = 0; nt < 8; ++nt) {
                    MMA_BF16(acc[mt][nt], ah[mt], bh[nt]);
                    MMA_BF16(acc[mt][nt], al[mt], bh[nt]);
                    MMA_BF16(acc[mt][nt], ah[mt], bl[nt]);
                }
        }
        if (kc < 3) {
            *(uint4*)(sm + ABUF(nxt, 0) + sOff)      = ph0;
            *(uint4*)(sm + ABUF(nxt, 0) + sOff + 16) = ph1;
            *(uint4*)(sm + ABUF(nxt, 1) + sOff)      = pl0;
            *(uint4*)(sm + ABUF(nxt, 1) + sOff + 16) = pl1;
            __syncthreads();
        }
    }

    // epilogue: + bias, ReLU, store fp32, optional fused BN stats
    int tr = lane >> 2, tc = (lane & 3) * 2;
    #pragma unroll
    for (int nt = 0; nt < 8; ++nt) {
        int col = wn + nt * 8 + tc;
        float2 bv = *(const float2*)(bias + col);
        float s0 = 0.f, s1 = 0.f, q0 = 0.f, q1 = 0.f;
        #pragma unroll
        for (int mt = 0; mt < 2; ++mt) {
            int row = r0 + wm + mt * 16 + tr;
            float v0 = fmaxf(acc[mt][nt][0] + bv.x, 0.f);
            float v1 = fmaxf(acc[mt][nt][1] + bv.y, 0.f);
            float v2 = fmaxf(acc[mt][nt][2] + bv.x, 0.f);
            float v3 = fmaxf(acc[mt][nt][3] + bv.y, 0.f);
            if (row < n)
                *(float2*)(C + (size_t)row * D + col) = make_float2(v0, v1);
            if (row + 8 < n)
                *(float2*)(C + (size_t)(row + 8) * D + col) = make_float2(v2, v3);
            if (do_stats) {
                if (row < n)     { s0 += v0; q0 += v0 * v0; s1 += v1; q1 += v1 * v1; }
                if (row + 8 < n) { s0 += v2; q0 += v2 * v2; s1 += v3; q1 += v3 * v3; }
            }
        }
        if (do_stats) {
            #pragma unroll
            for (int off = 4; off <= 16; off <<= 1) {
                s0 += __shfl_xor_sync(0xFFFFFFFFu, s0, off);
                s1 += __shfl_xor_sync(0xFFFFFFFFu, s1, off);
                q0 += __shfl_xor_sync(0xFFFFFFFFu, q0, off);
                q1 += __shfl_xor_sync(0xFFFFFFFFu, q1, off);
            }
            if (lane < 4) {
                int cc = wn + nt * 8 + lane * 2;
                atomicAdd(&s_stat[cc],         s0);
                atomicAdd(&s_stat[cc + 1],     s1);
                atomicAdd(&s_stat[D + cc],     q0);
                atomicAdd(&s_stat[D + cc + 1], q1);
            }
        }
    }
    if (do_stats) {
        __syncthreads();
        if (t < D) {
            atomicAdd(&g_sum[t],   s_stat[t]);
            atomicAdd(&g_sumsq[t], s_stat[D + t]);
        }
    }
}

// ---------------- 9: BatchNorm apply + cnt/cur cleanup -------------------
__global__ void k_bn(const float* __restrict__ h,
                     const float* __restrict__ gamma,
                     const float* __restrict__ beta,
                     float* __restrict__ out, int n) {
    int idx = blockIdx.x * blockDim.x + threadIdx.x;
    if (idx < n) { g_cnt[idx] = 0; g_cur[idx] = 0; }   // restore for next replay
    int total = n * (D / 4);
    if (idx >= total) return;
    int d0 = (idx & 31) * 4;
    float invN = 1.0f / (float)n;
    float4 v = ((const float4*)h)[idx];
    float vv[4] = {v.x, v.y, v.z, v.w};
    float res[4];
    #pragma unroll
    for (int s = 0; s < 4; ++s) {
        int d = d0 + s;
        float m   = g_sum[d] * invN;
        float var = g_sumsq[d] * invN - m * m;
        float inv = rsqrtf(var + EPSV);
        res[s] = gamma[d] * (vv[s] - m) * inv + beta[d];
    }
    ((float4*)out)[idx] = make_float4(res[0], res[1], res[2], res[3]);
}

// ---------------- launch ----------------
extern "C" void kernel_launch(void* const* d_in, const int* in_sizes, int n_in,
                              void* d_out, int out_size) {
    const float* x     = (const float*)d_in[0];
    const int*   ei    = (const int*)d_in[1];
    const float* W1    = (const float*)d_in[2];
    const float* b1    = (const float*)d_in[3];
    const float* W2    = (const float*)d_in[4];
    const float* b2    = (const float*)d_in[5];
    const float* gamma = (const float*)d_in[6];
    const float* beta  = (const float*)d_in[7];
    float* out = (float*)d_out;

    int n = in_sizes[0] / D;
    int e = in_sizes[1] / 2;
    const int* rows = ei;
    const int* cols = ei + e;

    float* bufO;
    __nv_bfloat16 *yhi, *ylo, *wh1, *wl1, *wh2, *wl2;
    cudaGetSymbolAddress((void**)&bufO, g_out);
    cudaGetSymbolAddress((void**)&yhi, g_Yhi);
    cudaGetSymbolAddress((void**)&ylo, g_Ylo);
    cudaGetSymbolAddress((void**)&wh1, g_WThi1);
    cudaGetSymbolAddress((void**)&wl1, g_WTlo1);
    cudaGetSymbolAddress((void**)&wh2, g_WThi2);
    cudaGetSymbolAddress((void**)&wl2, g_WTlo2);

    cudaFuncSetAttribute(k_gemm_mma, cudaFuncAttributeMaxDynamicSharedMemorySize,
                         GEMM_SMEM);

    int tb = 256;
    int nb_n  = (n + tb - 1) / tb;          // 196
    int nb_e  = (e + tb - 1) / tb;
    int nb_f4 = (n * (D / 4) + tb - 1) / tb;
    int gemm_grid = (n + 127) / 128;
    int agg_grid = 2048;

    // CSR build (9 launches total)
    k_deg<<<nb_e, tb>>>(cols, e);                      // 1 (+stats zero)
    k_scan1<<<nb_n, 256>>>(W1, W2, n);                 // 2 (+W split)
    k_scanF<<<nb_n, 256>>>(n, nb_n);                   // 3
    k_scatter<<<nb_e, tb>>>(rows, cols, e);            // 4 (<-- profile slot)

    // layer 1
    k_agg<<<agg_grid, 256>>>(x, yhi, ylo, n);          // 5
    k_gemm_mma<<<gemm_grid, 256, GEMM_SMEM>>>(yhi, ylo, wh1, wl1, b1, bufO, n, 0); // 6
    // layer 2
    k_agg<<<agg_grid, 256>>>(bufO, yhi, ylo, n);       // 7
    k_gemm_mma<<<gemm_grid, 256, GEMM_SMEM>>>(yhi, ylo, wh2, wl2, b2, bufO, n, 1); // 8

    // batchnorm (+cnt/cur cleanup)
    k_bn<<<nb_f4, tb>>>(bufO, gamma, beta, out, n);    // 9
}

// round 13
// speedup vs baseline: 1.8143x; 1.0028x over previous
#include <cuda_runtime.h>
#include <cuda_bf16.h>
#include <cstdint>

#define D 128
#define MAXN 50000
#define MAXE 600000
#define EPSV 1e-5f

// ---------------- scratch (zero-init at load; k_deg/k_bn restore) --------
__device__ int   g_cnt[MAXN];
__device__ int   g_cur[MAXN];
__device__ int   g_start[MAXN];
__device__ int   g_bsum[256];
__device__ float g_dis[MAXN];
__device__ int2  g_edge[MAXE];    // packed {row, dis[row] bits}
__device__ float g_out[(size_t)MAXN * D];
__device__ __nv_bfloat16 g_Yhi[(size_t)MAXN * D];
__device__ __nv_bfloat16 g_Ylo[(size_t)MAXN * D];
__device__ __nv_bfloat16 g_WThi1[D * D];
__device__ __nv_bfloat16 g_WTlo1[D * D];
__device__ __nv_bfloat16 g_WThi2[D * D];
__device__ __nv_bfloat16 g_WTlo2[D * D];
__device__ float g_sum[D];
__device__ float g_sumsq[D];

// ---------------- helpers ----------------
__device__ __forceinline__ uint32_t smem_u32(const void* p) {
    uint32_t a;
    asm("{ .reg .u64 t; cvta.to.shared.u64 t, %1; cvt.u32.u64 %0, t; }"
        : "=r"(a) : "l"(p));
    return a;
}

#define LDSM4(r0, r1, r2, r3, addr) \
    asm volatile("ldmatrix.sync.aligned.m8n8.x4.shared.b16 {%0,%1,%2,%3}, [%4];" \
        : "=r"(r0), "=r"(r1), "=r"(r2), "=r"(r3) : "r"(addr))

#define MMA_BF16(d, a, b) \
    asm volatile("mma.sync.aligned.m16n8k16.row.col.f32.bf16.bf16.f32 " \
        "{%0,%1,%2,%3}, {%4,%5,%6,%7}, {%8,%9}, {%0,%1,%2,%3};" \
        : "+f"((d)[0]), "+f"((d)[1]), "+f"((d)[2]), "+f"((d)[3]) \
        : "r"((a)[0]), "r"((a)[1]), "r"((a)[2]), "r"((a)[3]), \
          "r"((b)[0]), "r"((b)[1]))

__device__ __forceinline__ void split_bf16(float v, __nv_bfloat16& h, __nv_bfloat16& l) {
    h = __float2bfloat16_rn(v);
    l = __float2bfloat16_rn(v - __bfloat162float(h));
}

// ---------------- 1: degree histogram + stats zero -----------------------
__global__ void k_deg(const int* __restrict__ cols, int e) {
    int i = blockIdx.x * blockDim.x + threadIdx.x;
    if (i < e) atomicAdd(&g_cnt[cols[i]], 1);
    if (i < D) { g_sum[i] = 0.f; g_sumsq[i] = 0.f; }
}

// ---------------- 2: per-block scan + W split (fused) --------------------
__global__ void __launch_bounds__(256) k_scan1(const float* __restrict__ W1,
                                               const float* __restrict__ W2,
                                               int n) {
    __shared__ int sh[256];
    int t = threadIdx.x;
    int i = blockIdx.x * 256 + t;

    if (i < D * D) {
        int k = i >> 7, nn = i & 127;
        __nv_bfloat16 h, l;
        split_bf16(W1[i], h, l);
        g_WThi1[nn * D + k] = h;
        g_WTlo1[nn * D + k] = l;
        split_bf16(W2[i], h, l);
        g_WThi2[nn * D + k] = h;
        g_WTlo2[nn * D + k] = l;
    }

    int v = (i < n) ? g_cnt[i] : 0;
    sh[t] = v;
    __syncthreads();
    #pragma unroll
    for (int off = 1; off < 256; off <<= 1) {
        int u = (t >= off) ? sh[t - off] : 0;
        __syncthreads();
        sh[t] += u;
        __syncthreads();
    }
    if (i < n) g_start[i] = sh[t] - v;
    if (t == 255) g_bsum[blockIdx.x] = sh[255];
}

// ---------------- 3: block-offset add + dis ------------------------------
__global__ void __launch_bounds__(256) k_scanF(int n, int nb) {
    __shared__ int red[256];
    int t = threadIdx.x;
    int b = blockIdx.x;
    red[t] = (t < b && t < nb) ? g_bsum[t] : 0;
    __syncthreads();
    #pragma unroll
    for (int off = 128; off > 0; off >>= 1) {
        if (t < off) red[t] += red[t + off];
        __syncthreads();
    }
    int offset = red[0];
    int i = b * 256 + t;
    if (i < n) {
        g_start[i] += offset;
        g_dis[i] = rsqrtf((float)g_cnt[i] + 1.0f);
    }
}

// ---------------- 4: CSR scatter, packed (row, dis[row]) -----------------
__global__ void k_scatter(const int* __restrict__ rows,
                          const int* __restrict__ cols, int e) {
    int i = blockIdx.x * blockDim.x + threadIdx.x;
    if (i < e) {
        int r = rows[i];
        int c = cols[i];
        int p = g_start[c] + atomicAdd(&g_cur[c], 1);
        g_edge[p] = make_int2(r, __float_as_int(g_dis[r]));
    }
}

// ---------------- 5/7: aggregation Y = A_hat * src, 8-deep MLP -----------
__global__ void __launch_bounds__(256) k_agg(const float* __restrict__ src,
                                             __nv_bfloat16* __restrict__ outHi,
                                             __nv_bfloat16* __restrict__ outLo,
                                             int n) {
    int tid  = threadIdx.x;
    int lane = tid & 31;
    int wid  = tid >> 5;

    for (int c = blockIdx.x * 8 + wid; c < n; c += gridDim.x * 8) {
        int s0  = g_start[c];
        int end = s0 + g_cnt[c];
        float4 a0 = make_float4(0.f, 0.f, 0.f, 0.f);
        float4 a1 = a0, a2 = a0, a3 = a0;

        int j = s0;
        for (; j + 8 <= end; j += 8) {
            int2 e0 = __ldg(&g_edge[j + 0]);
            int2 e1 = __ldg(&g_edge[j + 1]);
            int2 e2 = __ldg(&g_edge[j + 2]);
            int2 e3 = __ldg(&g_edge[j + 3]);
            int2 e4 = __ldg(&g_edge[j + 4]);
            int2 e5 = __ldg(&g_edge[j + 5]);
            int2 e6 = __ldg(&g_edge[j + 6]);
            int2 e7 = __ldg(&g_edge[j + 7]);
            float4 v0 = *(const float4*)(src + (size_t)e0.x * D + lane * 4);
            float4 v1 = *(const float4*)(src + (size_t)e1.x * D + lane * 4);
            float4 v2 = *(const float4*)(src + (size_t)e2.x * D + lane * 4);
            float4 v3 = *(const float4*)(src + (size_t)e3.x * D + lane * 4);
            float4 v4 = *(const float4*)(src + (size_t)e4.x * D + lane * 4);
            float4 v5 = *(const float4*)(src + (size_t)e5.x * D + lane * 4);
            float4 v6 = *(const float4*)(src + (size_t)e6.x * D + lane * 4);
            float4 v7 = *(const float4*)(src + (size_t)e7.x * D + lane * 4);
            float d0 = __int_as_float(e0.y), d1 = __int_as_float(e1.y);
            float d2 = __int_as_float(e2.y), d3 = __int_as_float(e3.y);
            float d4 = __int_as_float(e4.y), d5 = __int_as_float(e5.y);
            float d6 = __int_as_float(e6.y), d7 = __int_as_float(e7.y);
            a0.x = fmaf(v0.x, d0, a0.x); a0.y = fmaf(v0.y, d0, a0.y);
            a0.z = fmaf(v0.z, d0, a0.z); a0.w = fmaf(v0.w, d0, a0.w);
            a1.x = fmaf(v1.x, d1, a1.x); a1.y = fmaf(v1.y, d1, a1.y);
            a1.z = fmaf(v1.z, d1, a1.z); a1.w = fmaf(v1.w, d1, a1.w);
            a2.x = fmaf(v2.x, d2, a2.x); a2.y = fmaf(v2.y, d2, a2.y);
            a2.z = fmaf(v2.z, d2, a2.z); a2.w = fmaf(v2.w, d2, a2.w);
            a3.x = fmaf(v3.x, d3, a3.x); a3.y = fmaf(v3.y, d3, a3.y);
            a3.z = fmaf(v3.z, d3, a3.z); a3.w = fmaf(v3.w, d3, a3.w);
            a0.x = fmaf(v4.x, d4, a0.x); a0.y = fmaf(v4.y, d4, a0.y);
            a0.z = fmaf(v4.z, d4, a0.z); a0.w = fmaf(v4.w, d4, a0.w);
            a1.x = fmaf(v5.x, d5, a1.x); a1.y = fmaf(v5.y, d5, a1.y);
            a1.z = fmaf(v5.z, d5, a1.z); a1.w = fmaf(v5.w, d5, a1.w);
            a2.x = fmaf(v6.x, d6, a2.x); a2.y = fmaf(v6.y, d6, a2.y);
            a2.z = fmaf(v6.z, d6, a2.z); a2.w = fmaf(v6.w, d6, a2.w);
            a3.x = fmaf(v7.x, d7, a3.x); a3.y = fmaf(v7.y, d7, a3.y);
            a3.z = fmaf(v7.z, d7, a3.z); a3.w = fmaf(v7.w, d7, a3.w);
        }
        for (; j < end; ++j) {
            int2 ee = __ldg(&g_edge[j]);
            float dr = __int_as_float(ee.y);
            float4 v = *(const float4*)(src + (size_t)ee.x * D + lane * 4);
            a0.x = fmaf(v.x, dr, a0.x); a0.y = fmaf(v.y, dr, a0.y);
            a0.z = fmaf(v.z, dr, a0.z); a0.w = fmaf(v.w, dr, a0.w);
        }
        float4 acc;
        acc.x = (a0.x + a1.x) + (a2.x + a3.x);
        acc.y = (a0.y + a1.y) + (a2.y + a3.y);
        acc.z = (a0.z + a1.z) + (a2.z + a3.z);
        acc.w = (a0.w + a1.w) + (a2.w + a3.w);

        float dc = g_dis[c];
        float sc = dc * dc;
        float4 hc = *(const float4*)(src + (size_t)c * D + lane * 4);
        float4 r4;
        r4.x = fmaf(acc.x, dc, hc.x * sc);
        r4.y = fmaf(acc.y, dc, hc.y * sc);
        r4.z = fmaf(acc.z, dc, hc.z * sc);
        r4.w = fmaf(acc.w, dc, hc.w * sc);

        __nv_bfloat16 hh[4], ll[4];
        split_bf16(r4.x, hh[0], ll[0]);
        split_bf16(r4.y, hh[1], ll[1]);
        split_bf16(r4.z, hh[2], ll[2]);
        split_bf16(r4.w, hh[3], ll[3]);
        *(uint2*)(outHi + (size_t)c * D + lane * 4) = *(uint2*)hh;
        *(uint2*)(outLo + (size_t)c * D + lane * 4) = *(uint2*)ll;
    }
}

// ------ 6/8: bf16 mma GEMM, 128x64 tile, 2 CTAs/SM, fused BN stats -------
#define WSTRIDE 136
#define ABSTRIDE 40
#define SM_WHI 0
#define SM_WLO 17408
#define SM_A   34816
#define ABUF(buf, dt) (SM_A + (buf) * 20480 + (dt) * 10240)
#define GEMM_SMEM 75776

__global__ void __launch_bounds__(256, 2)
k_gemm_mma(const __nv_bfloat16* __restrict__ Ahi,
           const __nv_bfloat16* __restrict__ Alo,
           const __nv_bfloat16* __restrict__ Whi,
           const __nv_bfloat16* __restrict__ Wlo,
           const float* __restrict__ bias,
           float* __restrict__ C, int n, int do_stats) {
    extern __shared__ __align__(16) char sm[];
    __shared__ float s_stat[2 * 64];
    uint32_t sb = smem_u32(sm);
    int t = threadIdx.x, lane = t & 31, wid = t >> 5;
    int r0 = blockIdx.x * 128;
    int c0 = blockIdx.y * 64;                 // column half
    int wm = (wid >> 1) * 32;                 // 4 row groups of 32
    int wn = (wid & 1) * 32;                  // 2 col groups of 32

    // stage W hi/lo [64 n][128 k] — 4 uint4 (=32 bf16) per thread per tensor
    {
        int row = t >> 2, q = t & 3;          // row 0..63, k quarter 0..3
        const uint4* gh = (const uint4*)(Whi + (size_t)(c0 + row) * D + q * 32);
        const uint4* gl = (const uint4*)(Wlo + (size_t)(c0 + row) * D + q * 32);
        uint4* shh = (uint4*)(sm + SM_WHI + (row * WSTRIDE + q * 32) * 2);
        uint4* shl = (uint4*)(sm + SM_WLO + (row * WSTRIDE + q * 32) * 2);
        #pragma unroll
        for (int j = 0; j < 4; ++j) { shh[j] = gh[j]; shl[j] = gl[j]; }
    }
    if (do_stats && t < 2 * 64) s_stat[t] = 0.f;

    int qa = lane >> 3, la = lane & 7;
    int ra = (qa & 1) * 8 + la;
    int ka = (qa >> 1) * 8;
    int nb = (qa >> 1) * 8 + la;
    int kb = (qa & 1) * 8;

    uint32_t aHiBase[2], aLoBase[2];
    #pragma unroll
    for (int bf = 0; bf < 2; ++bf) {
        aHiBase[bf] = sb + ABUF(bf, 0) + ((wm + ra) * ABSTRIDE + ka) * 2;
        aLoBase[bf] = sb + ABUF(bf, 1) + ((wm + ra) * ABSTRIDE + ka) * 2;
    }
    uint32_t bHiB = sb + SM_WHI + ((wn + nb) * WSTRIDE + kb) * 2;
    uint32_t bLoB = sb + SM_WLO + ((wn + nb) * WSTRIDE + kb) * 2;

    float acc[2][4][4];
    #pragma unroll
    for (int mt = 0; mt < 2; ++mt)
        #pragma unroll
        for (int nt = 0; nt < 4; ++nt)
            #pragma unroll
            for (int q = 0; q < 4; ++q) acc[mt][nt][q] = 0.f;

    int arow = t >> 1, apart = t & 1;
    int arg = r0 + arow; if (arg >= n) arg = n - 1;
    const uint4* gAh = (const uint4*)(Ahi + (size_t)arg * D);
    const uint4* gAl = (const uint4*)(Alo + (size_t)arg * D);
    int gidx = apart * 2;
    uint32_t sOff = (uint32_t)((arow * ABSTRIDE + apart * 16) * 2);

    // prologue: chunk 0 -> buf 0
    {
        uint4 h0 = gAh[gidx], h1 = gAh[gidx + 1];
        uint4 l0 = gAl[gidx], l1 = gAl[gidx + 1];
        *(uint4*)(sm + ABUF(0, 0) + sOff)      = h0;
        *(uint4*)(sm + ABUF(0, 0) + sOff + 16) = h1;
        *(uint4*)(sm + ABUF(0, 1) + sOff)      = l0;
        *(uint4*)(sm + ABUF(0, 1) + sOff + 16) = l1;
    }
    __syncthreads();

    #pragma unroll
    for (int kc = 0; kc < 4; ++kc) {
        int cur = kc & 1, nxt = cur ^ 1;
        uint4 ph0, ph1, pl0, pl1;
        if (kc < 3) {
            ph0 = gAh[(kc + 1) * 4 + gidx]; ph1 = gAh[(kc + 1) * 4 + gidx + 1];
            pl0 = gAl[(kc + 1) * 4 + gidx]; pl1 = gAl[(kc + 1) * 4 + gidx + 1];
        }
        #pragma unroll
        for (int s = 0; s < 2; ++s) {
            uint32_t ah[2][4], al[2][4], bh[4][2], bl[4][2];
            #pragma unroll
            for (int mt = 0; mt < 2; ++mt) {
                uint32_t ao = (uint32_t)(mt * 16 * ABSTRIDE * 2 + s * 32);
                LDSM4(ah[mt][0], ah[mt][1], ah[mt][2], ah[mt][3], aHiBase[cur] + ao);
                LDSM4(al[mt][0], al[mt][1], al[mt][2], al[mt][3], aLoBase[cur] + ao);
            }
            #pragma unroll
            for (int p = 0; p < 2; ++p) {
                uint32_t bo = (uint32_t)(p * 16 * WSTRIDE * 2 + (kc * 32 + s * 16) * 2);
                LDSM4(bh[2*p][0], bh[2*p][1], bh[2*p+1][0], bh[2*p+1][1], bHiB + bo);
                LDSM4(bl[2*p][0], bl[2*p][1], bl[2*p+1][0], bl[2*p+1][1], bLoB + bo);
            }
            #pragma unroll
            for (int mt = 0; mt < 2; ++mt)
                #pragma unroll
                for (int nt = 0; nt < 4; ++nt) {
                    MMA_BF16(acc[mt][nt], ah[mt], bh[nt]);
                    MMA_BF16(acc[mt][nt], al[mt], bh[nt]);
                    MMA_BF16(acc[mt][nt], ah[mt], bl[nt]);
                }
        }
        if (kc < 3) {
            *(uint4*)(sm + ABUF(nxt, 0) + sOff)      = ph0;
            *(uint4*)(sm + ABUF(nxt, 0) + sOff + 16) = ph1;
            *(uint4*)(sm + ABUF(nxt, 1) + sOff)      = pl0;
            *(uint4*)(sm + ABUF(nxt, 1) + sOff + 16) = pl1;
            __syncthreads();
        }
    }

    // epilogue: + bias, ReLU, store fp32, optional fused BN stats
    int tr = lane >> 2, tc = (lane & 3) * 2;
    #pragma unroll
    for (int nt = 0; nt < 4; ++nt) {
        int col = wn + nt * 8 + tc;           // local 0..63
        int gc  = c0 + col;
        float2 bv = *(const float2*)(bias + gc);
        float s0 = 0.f, s1 = 0.f, q0 = 0.f, q1 = 0.f;
        #pragma unroll
        for (int mt = 0; mt < 2; ++mt) {
            int row = r0 + wm + mt * 16 + tr;
            float v0 = fmaxf(acc[mt][nt][0] + bv.x, 0.f);
            float v1 = fmaxf(acc[mt][nt][1] + bv.y, 0.f);
            float v2 = fmaxf(acc[mt][nt][2] + bv.x, 0.f);
            float v3 = fmaxf(acc[mt][nt][3] + bv.y, 0.f);
            if (row < n)
                *(float2*)(C + (size_t)row * D + gc) = make_float2(v0, v1);
            if (row + 8 < n)
                *(float2*)(C + (size_t)(row + 8) * D + gc) = make_float2(v2, v3);
            if (do_stats) {
                if (row < n)     { s0 += v0; q0 += v0 * v0; s1 += v1; q1 += v1 * v1; }
                if (row + 8 < n) { s0 += v2; q0 += v2 * v2; s1 += v3; q1 += v3 * v3; }
            }
        }
        if (do_stats) {
            #pragma unroll
            for (int off = 4; off <= 16; off <<= 1) {
                s0 += __shfl_xor_sync(0xFFFFFFFFu, s0, off);
                s1 += __shfl_xor_sync(0xFFFFFFFFu, s1, off);
                q0 += __shfl_xor_sync(0xFFFFFFFFu, q0, off);
                q1 += __shfl_xor_sync(0xFFFFFFFFu, q1, off);
            }
            if (lane < 4) {
                int cc = wn + nt * 8 + lane * 2;
                atomicAdd(&s_stat[cc],          s0);
                atomicAdd(&s_stat[cc + 1],      s1);
                atomicAdd(&s_stat[64 + cc],     q0);
                atomicAdd(&s_stat[64 + cc + 1], q1);
            }
        }
    }
    if (do_stats) {
        __syncthreads();
        if (t < 64) {
            atomicAdd(&g_sum[c0 + t],   s_stat[t]);
            atomicAdd(&g_sumsq[c0 + t], s_stat[64 + t]);
        }
    }
}

// ---------------- 9: BatchNorm apply + cnt/cur cleanup -------------------
__global__ void k_bn(const float* __restrict__ h,
                     const float* __restrict__ gamma,
                     const float* __restrict__ beta,
                     float* __restrict__ out, int n) {
    int idx = blockIdx.x * blockDim.x + threadIdx.x;
    if (idx < n) { g_cnt[idx] = 0; g_cur[idx] = 0; }
    int total = n * (D / 4);
    if (idx >= total) return;
    int d0 = (idx & 31) * 4;
    float invN = 1.0f / (float)n;
    float4 v = ((const float4*)h)[idx];
    float vv[4] = {v.x, v.y, v.z, v.w};
    float res[4];
    #pragma unroll
    for (int s = 0; s < 4; ++s) {
        int d = d0 + s;
        float m   = g_sum[d] * invN;
        float var = g_sumsq[d] * invN - m * m;
        float inv = rsqrtf(var + EPSV);
        res[s] = gamma[d] * (vv[s] - m) * inv + beta[d];
    }
    ((float4*)out)[idx] = make_float4(res[0], res[1], res[2], res[3]);
}

// ---------------- launch ----------------
extern "C" void kernel_launch(void* const* d_in, const int* in_sizes, int n_in,
                              void* d_out, int out_size) {
    const float* x     = (const float*)d_in[0];
    const int*   ei    = (const int*)d_in[1];
    const float* W1    = (const float*)d_in[2];
    const float* b1    = (const float*)d_in[3];
    const float* W2    = (const float*)d_in[4];
    const float* b2    = (const float*)d_in[5];
    const float* gamma = (const float*)d_in[6];
    const float* beta  = (const float*)d_in[7];
    float* out = (float*)d_out;

    int n = in_sizes[0] / D;
    int e = in_sizes[1] / 2;
    const int* rows = ei;
    const int* cols = ei + e;

    float* bufO;
    __nv_bfloat16 *yhi, *ylo, *wh1, *wl1, *wh2, *wl2;
    cudaGetSymbolAddress((void**)&bufO, g_out);
    cudaGetSymbolAddress((void**)&yhi, g_Yhi);
    cudaGetSymbolAddress((void**)&ylo, g_Ylo);
    cudaGetSymbolAddress((void**)&wh1, g_WThi1);
    cudaGetSymbolAddress((void**)&wl1, g_WTlo1);
    cudaGetSymbolAddress((void**)&wh2, g_WThi2);
    cudaGetSymbolAddress((void**)&wl2, g_WTlo2);

    cudaFuncSetAttribute(k_gemm_mma, cudaFuncAttributeMaxDynamicSharedMemorySize,
                         GEMM_SMEM);

    int tb = 256;
    int nb_n  = (n + tb - 1) / tb;
    int nb_e  = (e + tb - 1) / tb;
    int nb_f4 = (n * (D / 4) + tb - 1) / tb;
    dim3 gemm_grid((n + 127) / 128, 2);
    int agg_grid = 2048;

    // CSR build
    k_deg<<<nb_e, tb>>>(cols, e);                      // 1 (+stats zero)
    k_scan1<<<nb_n, 256>>>(W1, W2, n);                 // 2 (+W split)
    k_scanF<<<nb_n, 256>>>(n, nb_n);                   // 3
    k_scatter<<<nb_e, tb>>>(rows, cols, e);            // 4 (<-- profile slot)

    // layer 1
    k_agg<<<agg_grid, 256>>>(x, yhi, ylo, n);          // 5
    k_gemm_mma<<<gemm_grid, 256, GEMM_SMEM>>>(yhi, ylo, wh1, wl1, b1, bufO, n, 0); // 6
    // layer 2
    k_agg<<<agg_grid, 256>>>(bufO, yhi, ylo, n);       // 7
    k_gemm_mma<<<gemm_grid, 256, GEMM_SMEM>>>(yhi, ylo, wh2, wl2, b2, bufO, n, 1); // 8

    // batchnorm (+cnt/cur cleanup)
    k_bn<<<nb_f4, tb>>>(bufO, gamma, beta, out, n);    // 9
}